// round 11
// baseline (speedup 1.0000x reference)
#include <cuda_runtime.h>
#include <cuda_bf16.h>
#include <cstdint>
#include <math.h>

#define BB 32
#define TT 4096
#define DIN 256
#define HID 512
#define AD 259
#define KLIFT 64
#define DMODEL 1024
#define KSEL 32
#define PGD_STEPS 60

// ---------------- scratch (device globals; no allocation allowed) ----------
__device__ float g_sal[BB * TT];
__device__ float g_spart[4][BB * TT];        // per-N-tile partial saliency dot
__device__ float g_xpart[16 * BB * DIN];
__device__ float g_xmean[BB * DIN];
__device__ float g_msal[BB];
__device__ int   g_topidx[BB * KSEL];
// W1 pre-fragmented for mma.sync B operand: [n_tile 64][k_chunk 16][lane 32]
__device__ uint2 g_BfH[64 * 16 * 32];
__device__ uint2 g_BfL[64 * 16 * 32];

__device__ __forceinline__ uint32_t pack_bf2(__nv_bfloat16 a, __nv_bfloat16 b) {
    return (uint32_t)__bfloat16_as_ushort(a) | ((uint32_t)__bfloat16_as_ushort(b) << 16);
}

// mma.sync m16n8k16 row.col f32.bf16.bf16.f32 (portable PTX, HMMA pipe)
__device__ __forceinline__ void mma_bf16(float* d, const uint32_t* a, const uint32_t* b) {
    asm volatile(
        "mma.sync.aligned.m16n8k16.row.col.f32.bf16.bf16.f32 "
        "{%0,%1,%2,%3}, {%4,%5,%6,%7}, {%8,%9}, {%0,%1,%2,%3};"
        : "+f"(d[0]), "+f"(d[1]), "+f"(d[2]), "+f"(d[3])
        : "r"(a[0]), "r"(a[1]), "r"(a[2]), "r"(a[3]), "r"(b[0]), "r"(b[1]));
}

// ldmatrix x4: loads 4 8x8 b16 matrices; lane supplies one 16B row address.
__device__ __forceinline__ void ldsm_x4(uint32_t* r, uint32_t saddr) {
    asm volatile(
        "ldmatrix.sync.aligned.m8n8.x4.shared.b16 {%0,%1,%2,%3}, [%4];"
        : "=r"(r[0]), "=r"(r[1]), "=r"(r[2]), "=r"(r[3]) : "r"(saddr));
}

__device__ __forceinline__ uint32_t smem_u32(const void* p) {
    return (uint32_t)__cvta_generic_to_shared(p);
}
// 16B-unit swizzle: distinct banks for all STS/LDSM phases
__device__ __forceinline__ uint32_t su16(uint32_t u) { return u ^ ((u >> 3) & 1u); }

// trunc-split of 8 contiguous floats (2 float4) -> hi uint4 (PRMT) + lo uint4
__device__ __forceinline__ void split8(float4 v0, float4 v1, uint4* hi, uint4* lo) {
    uint32_t b0 = __float_as_uint(v0.x), b1 = __float_as_uint(v0.y);
    uint32_t b2 = __float_as_uint(v0.z), b3 = __float_as_uint(v0.w);
    uint32_t b4 = __float_as_uint(v1.x), b5 = __float_as_uint(v1.y);
    uint32_t b6 = __float_as_uint(v1.z), b7 = __float_as_uint(v1.w);
    hi->x = __byte_perm(b0, b1, 0x7632);
    hi->y = __byte_perm(b2, b3, 0x7632);
    hi->z = __byte_perm(b4, b5, 0x7632);
    hi->w = __byte_perm(b6, b7, 0x7632);
    float l0 = v0.x - __uint_as_float(b0 & 0xFFFF0000u);
    float l1 = v0.y - __uint_as_float(b1 & 0xFFFF0000u);
    float l2 = v0.z - __uint_as_float(b2 & 0xFFFF0000u);
    float l3 = v0.w - __uint_as_float(b3 & 0xFFFF0000u);
    float l4 = v1.x - __uint_as_float(b4 & 0xFFFF0000u);
    float l5 = v1.y - __uint_as_float(b5 & 0xFFFF0000u);
    float l6 = v1.z - __uint_as_float(b6 & 0xFFFF0000u);
    float l7 = v1.w - __uint_as_float(b7 & 0xFFFF0000u);
    __nv_bfloat162 p0 = __float22bfloat162_rn(make_float2(l0, l1));
    __nv_bfloat162 p1 = __float22bfloat162_rn(make_float2(l2, l3));
    __nv_bfloat162 p2 = __float22bfloat162_rn(make_float2(l4, l5));
    __nv_bfloat162 p3 = __float22bfloat162_rn(make_float2(l6, l7));
    lo->x = *(uint32_t*)&p0;
    lo->y = *(uint32_t*)&p1;
    lo->z = *(uint32_t*)&p2;
    lo->w = *(uint32_t*)&p3;
}

// ---------------------------------------------------------------------------
// Kernel 0: W1 -> bf16 hi/lo (RNE) in mma B-fragment order.
// ---------------------------------------------------------------------------
__global__ void k_convert_w(const float* __restrict__ W1)
{
    const int nt = blockIdx.x, kc = blockIdx.y, l = threadIdx.x;
    const int n = nt * 8 + (l >> 2);
    const int k = kc * 16 + (l & 3) * 2;
    float v00 = W1[(size_t)k * HID + n];
    float v01 = W1[(size_t)(k + 1) * HID + n];
    float v10 = W1[(size_t)(k + 8) * HID + n];
    float v11 = W1[(size_t)(k + 9) * HID + n];
    __nv_bfloat16 h00 = __float2bfloat16(v00), h01 = __float2bfloat16(v01);
    __nv_bfloat16 h10 = __float2bfloat16(v10), h11 = __float2bfloat16(v11);
    __nv_bfloat16 l00 = __float2bfloat16(v00 - __bfloat162float(h00));
    __nv_bfloat16 l01 = __float2bfloat16(v01 - __bfloat162float(h01));
    __nv_bfloat16 l10 = __float2bfloat16(v10 - __bfloat162float(h10));
    __nv_bfloat16 l11 = __float2bfloat16(v11 - __bfloat162float(h11));
    const int o = (nt * 16 + kc) * 32 + l;
    g_BfH[o] = make_uint2(pack_bf2(h00, h01), pack_bf2(h10, h11));
    g_BfL[o] = make_uint2(pack_bf2(l00, l01), pack_bf2(l10, l11));
}

// ---------------------------------------------------------------------------
// Kernel 1: bf16-split GEMM via mma.sync (AhBh + AlBh + AhBl)
// 4-deep smem ring: iteration s consumes buf s%4, stores chunk s+2 into
// (s+2)%4; __syncthreads only after odd s  (8 barriers instead of 16).
// STS.128 (full 16B units per thread). m64n32 warp tile; n-fastest grid.
// ---------------------------------------------------------------------------
__global__ __launch_bounds__(256, 2) void k_gemm_part(
    const float* __restrict__ x, const float* __restrict__ b1,
    const float* __restrict__ w_sal)
{
    __shared__ __align__(16) unsigned char sA[4][2][4096];
    __shared__ float part[4][128];
    __shared__ float sB1[128], sWs[128];

    const int tid = threadIdx.x;
    const int n0 = blockIdx.x * 128;    // n-tile fastest: 4 CTAs share x m-tile
    const int m0 = blockIdx.y * 128;
    const int lane = tid & 31, wid = tid >> 5;
    const int wm = (wid >> 2) * 64, wn = (wid & 3) * 32;
    const int g = lane >> 2, t = lane & 3;
    const int ntbase = (n0 >> 3) + ((wid & 3) * 4);

    if (tid < 128) { sB1[tid] = b1[n0 + tid]; sWs[tid] = w_sal[n0 + tid]; }

    // A mapping: row = tid>>1 (0..127), cu = tid&1 (8 contiguous floats)
    const int arow = tid >> 1, acu = tid & 1;
    const uint32_t stsOff = su16((uint32_t)(arow * 2 + acu)) * 16;
    const float* aptr = &x[(size_t)(m0 + arow) * DIN + acu * 8];

    uint32_t frOff[4];
    {
        const int r8 = lane & 7, hr = (lane >> 3) & 1, hc = (lane >> 4) & 1;
#pragma unroll
        for (int mi = 0; mi < 4; mi++) {
            uint32_t row = (uint32_t)(wm + mi * 16 + hr * 8 + r8);
            frOff[mi] = su16(row * 2 + (uint32_t)hc) * 16;
        }
    }
    const uint32_t base0 = smem_u32(&sA[0][0][0]);

    float acc[4][4][4];
#pragma unroll
    for (int mi = 0; mi < 4; mi++)
#pragma unroll
        for (int ni = 0; ni < 4; ni++)
#pragma unroll
            for (int q = 0; q < 4; q++) acc[mi][ni][q] = 0.f;

    // ---- prologue: chunks 0 and 1 into bufs 0,1; prefetch chunk 2 ----
    float4 pa0, pa1;
    {
        pa0 = *(const float4*)(aptr + 0);
        pa1 = *(const float4*)(aptr + 4);
        uint4 h, l;
        split8(pa0, pa1, &h, &l);
        *(uint4*)&sA[0][0][stsOff] = h;
        *(uint4*)&sA[0][1][stsOff] = l;
        pa0 = *(const float4*)(aptr + 16);
        pa1 = *(const float4*)(aptr + 20);
        split8(pa0, pa1, &h, &l);
        *(uint4*)&sA[1][0][stsOff] = h;
        *(uint4*)&sA[1][1][stsOff] = l;
    }
    __syncthreads();
    pa0 = *(const float4*)(aptr + 32);
    pa1 = *(const float4*)(aptr + 36);

#pragma unroll
    for (int s = 0; s < 16; s++) {
        const int buf = s & 3;
        const uint32_t baseH = base0 + buf * 8192;
        const uint32_t baseL = baseH + 4096;

        // ---- B fragments for chunk s: coalesced LDG.64 from L2 ----
        uint2 fbh[4], fbl[4];
#pragma unroll
        for (int ni = 0; ni < 4; ni++) {
            const int o = ((ntbase + ni) * 16 + s) * 32 + lane;
            fbh[ni] = g_BfH[o];
            fbl[ni] = g_BfL[o];
        }
        // ---- STS chunk s+2 (prefetched) into buf (s+2)%4 ----
        if (s < 14) {
            uint4 h, l;
            split8(pa0, pa1, &h, &l);
            const int wb = (s + 2) & 3;
            *(uint4*)&sA[wb][0][stsOff] = h;
            *(uint4*)&sA[wb][1][stsOff] = l;
        }
        // ---- prefetch chunk s+3 ----
        if (s < 13) {
            pa0 = *(const float4*)(aptr + (s + 3) * 16);
            pa1 = *(const float4*)(aptr + (s + 3) * 16 + 4);
        }

        uint32_t bh[4][2], bl[4][2];
#pragma unroll
        for (int ni = 0; ni < 4; ni++) {
            bh[ni][0] = fbh[ni].x; bh[ni][1] = fbh[ni].y;
            bl[ni][0] = fbl[ni].x; bl[ni][1] = fbl[ni].y;
        }
        uint32_t ah[4][4], al[4][4];
#pragma unroll
        for (int mi = 0; mi < 4; mi++) ldsm_x4(ah[mi], baseH + frOff[mi]);
#pragma unroll
        for (int mi = 0; mi < 4; mi++)
#pragma unroll
            for (int ni = 0; ni < 4; ni++)
                mma_bf16(acc[mi][ni], ah[mi], bh[ni]);
#pragma unroll
        for (int mi = 0; mi < 4; mi++)
#pragma unroll
            for (int ni = 0; ni < 4; ni++)
                mma_bf16(acc[mi][ni], ah[mi], bl[ni]);
#pragma unroll
        for (int mi = 0; mi < 4; mi++) ldsm_x4(al[mi], baseL + frOff[mi]);
#pragma unroll
        for (int mi = 0; mi < 4; mi++)
#pragma unroll
            for (int ni = 0; ni < 4; ni++)
                mma_bf16(acc[mi][ni], al[mi], bh[ni]);

        if (s & 1) __syncthreads();
    }

    // ---- epilogue: tanh + w_sal dot over this CTA's 128 columns ----
    float rsum[4][2];
#pragma unroll
    for (int mi = 0; mi < 4; mi++) { rsum[mi][0] = 0.f; rsum[mi][1] = 0.f; }
#pragma unroll
    for (int mi = 0; mi < 4; mi++)
#pragma unroll
        for (int ni = 0; ni < 4; ni++) {
            int c0 = wn + ni * 8 + t * 2;
            float w0 = sWs[c0], w1 = sWs[c0 + 1];
            float bb0 = sB1[c0], bb1 = sB1[c0 + 1];
            rsum[mi][0] += tanhf(acc[mi][ni][0] + bb0) * w0
                         + tanhf(acc[mi][ni][1] + bb1) * w1;
            rsum[mi][1] += tanhf(acc[mi][ni][2] + bb0) * w0
                         + tanhf(acc[mi][ni][3] + bb1) * w1;
        }
    __syncthreads();   // protect part[] reuse after mainloop
#pragma unroll
    for (int mi = 0; mi < 4; mi++)
#pragma unroll
        for (int sel = 0; sel < 2; sel++) {
            float v = rsum[mi][sel];
            v += __shfl_xor_sync(0xffffffffu, v, 1);
            v += __shfl_xor_sync(0xffffffffu, v, 2);
            if (t == 0) part[wid & 3][wm + mi * 16 + sel * 8 + g] = v;
        }
    __syncthreads();
    if (tid < 128) {
        float v = ((part[0][tid] + part[1][tid]) + part[2][tid]) + part[3][tid];
        g_spart[blockIdx.x][m0 + tid] = v;
    }
}

// ---------------------------------------------------------------------------
// Kernel 2a/2b: mean of x over T per batch (deterministic two-stage)
// ---------------------------------------------------------------------------
__global__ void k_xmean_part(const float* __restrict__ x)
{
    int b = blockIdx.x, ch = blockIdx.y, d = threadIdx.x;
    const float* base = x + ((size_t)b * TT + ch * 256) * DIN + d;
    float acc = 0.f;
    for (int t = 0; t < 256; t++) acc += base[(size_t)t * DIN];
    g_xpart[(ch * BB + b) * DIN + d] = acc;
}
__global__ void k_xmean_fin()
{
    int b = blockIdx.x, d = threadIdx.x;
    float acc = 0.f;
    for (int ch = 0; ch < 16; ch++) acc += g_xpart[(ch * BB + b) * DIN + d];
    g_xmean[b * DIN + d] = acc * (1.0f / TT);
}

// ---------------------------------------------------------------------------
// Kernel 3: fused sal-finalize + PGD selector (warm-started Newton tau,
// 1-sync block reduces), y_star out, mean_sal, exact top-32.
// ---------------------------------------------------------------------------
__global__ __launch_bounds__(1024) void k_selector(
    const float* __restrict__ b_sal, float* __restrict__ d_out)
{
    __shared__ float ysA[TT];
    __shared__ float ysB[TT];
    __shared__ float redS[2][32], redC[2][32];
    __shared__ float redT[2][32];
    __shared__ int   redi[2][32];

    const int b = blockIdx.x;
    const int tid = threadIdx.x;
    const int lane = tid & 31, wid = tid >> 5;
    const int i0 = tid * 4;

    float4 p0 = *(const float4*)&g_spart[0][b * TT + i0];
    float4 p1 = *(const float4*)&g_spart[1][b * TT + i0];
    float4 p2 = *(const float4*)&g_spart[2][b * TT + i0];
    float4 p3 = *(const float4*)&g_spart[3][b * TT + i0];
    const float bs = b_sal[0];
    float s[4];
    {
        float z0 = ((p0.x + p1.x) + p2.x) + p3.x + bs;
        float z1 = ((p0.y + p1.y) + p2.y) + p3.y + bs;
        float z2 = ((p0.z + p1.z) + p2.z) + p3.z + bs;
        float z3 = ((p0.w + p1.w) + p2.w) + p3.w + bs;
        s[0] = fmaxf(z0, 0.f) + log1pf(expf(-fabsf(z0)));
        s[1] = fmaxf(z1, 0.f) + log1pf(expf(-fabsf(z1)));
        s[2] = fmaxf(z2, 0.f) + log1pf(expf(-fabsf(z2)));
        s[3] = fmaxf(z3, 0.f) + log1pf(expf(-fabsf(z3)));
    }
    *(float4*)&g_sal[b * TT + i0] = make_float4(s[0], s[1], s[2], s[3]);

    float y[4] = {0.0078125f, 0.0078125f, 0.0078125f, 0.0078125f};
    ysA[i0] = y[0]; ysA[i0 + 1] = y[1]; ysA[i0 + 2] = y[2]; ysA[i0 + 3] = y[3];
    __syncthreads();

    float tau_prev = 0.f;
    for (int step = 0; step < PGD_STEPS; step++) {
        const float* rd = (step & 1) ? ysB : ysA;
        float*       wr = (step & 1) ? ysA : ysB;
        float l1 = (i0 > 0) ? rd[i0 - 1] : 0.f;
        float l2 = (i0 > 0) ? rd[i0 - 2] : 0.f;
        float r1 = (i0 + 4 < TT) ? rd[i0 + 4] : 0.f;
        float r2 = (i0 + 4 < TT) ? rd[i0 + 5] : 0.f;
        float nb[4];
        nb[0] = ((y[1] + l1) + y[2]) + l2;
        nb[1] = ((y[2] + y[0]) + y[3]) + l1;
        nb[2] = ((y[3] + y[1]) + r1) + y[0];
        nb[3] = ((r1 + y[2]) + r2) + y[1];

        float z[4];
#pragma unroll
        for (int q = 0; q < 4; q++) {
            float g = (s[q] - y[q]) - 0.5f * nb[q];
            z[q] = fminf(fmaxf(y[q] + 0.1f * g, 0.f), 1.f);
        }

        float tau = tau_prev;
        for (int it = 0; it < 24; it++) {
            const int p = it & 1;
            float ls = 0.f, lc = 0.f;
#pragma unroll
            for (int q = 0; q < 4; q++)
                if (z[q] > tau) { ls += z[q]; lc += 1.f; }
#pragma unroll
            for (int o = 16; o; o >>= 1) {
                ls += __shfl_xor_sync(0xffffffffu, ls, o);
                lc += __shfl_xor_sync(0xffffffffu, lc, o);
            }
            if (lane == 0) { redS[p][wid] = ls; redC[p][wid] = lc; }
            __syncthreads();
            float S = redS[p][lane], C = redC[p][lane];
#pragma unroll
            for (int o = 16; o; o >>= 1) {
                S += __shfl_xor_sync(0xffffffffu, S, o);
                C += __shfl_xor_sync(0xffffffffu, C, o);
            }
            float tnew = (C >= 1.f) ? fmaxf((S - 32.f) / C, 0.f) : 0.f;
            if (tnew == tau) break;
            tau = tnew;
        }
        tau_prev = tau;
#pragma unroll
        for (int q = 0; q < 4; q++)
            y[q] = fminf(fmaxf(z[q] - tau, 0.f), 1.f);
        wr[i0] = y[0]; wr[i0 + 1] = y[1]; wr[i0 + 2] = y[2]; wr[i0 + 3] = y[3];
        __syncthreads();
    }

    float* outY = d_out + (size_t)BB * KSEL * DMODEL + (size_t)b * TT;
    *(float4*)&outY[i0] = make_float4(y[0], y[1], y[2], y[3]);

    {
        float ms = ((s[0] + s[1]) + s[2]) + s[3];
#pragma unroll
        for (int o = 16; o; o >>= 1) ms += __shfl_xor_sync(0xffffffffu, ms, o);
        if (lane == 0) redS[0][wid] = ms;
        __syncthreads();
        if (tid < 32) {
            float v = redS[0][lane];
#pragma unroll
            for (int o = 16; o; o >>= 1) v += __shfl_xor_sync(0xffffffffu, v, o);
            if (lane == 0) g_msal[b] = v * (1.0f / TT);
        }
        __syncthreads();
    }

    float mval[4] = {y[0], y[1], y[2], y[3]};
    for (int sel = 0; sel < KSEL; sel++) {
        const int p = sel & 1;
        float bv = -1.f; int bi = TT;
#pragma unroll
        for (int q = 0; q < 4; q++)
            if (mval[q] > bv) { bv = mval[q]; bi = i0 + q; }
#pragma unroll
        for (int o = 16; o; o >>= 1) {
            float ov = __shfl_xor_sync(0xffffffffu, bv, o);
            int   oi = __shfl_xor_sync(0xffffffffu, bi, o);
            if (ov > bv || (ov == bv && oi < bi)) { bv = ov; bi = oi; }
        }
        if (lane == 0) { redT[p][wid] = bv; redi[p][wid] = bi; }
        __syncthreads();
        bv = redT[p][lane]; bi = redi[p][lane];
#pragma unroll
        for (int o = 16; o; o >>= 1) {
            float ov = __shfl_xor_sync(0xffffffffu, bv, o);
            int   oi = __shfl_xor_sync(0xffffffffu, bi, o);
            if (ov > bv || (ov == bv && oi < bi)) { bv = ov; bi = oi; }
        }
        if (tid == 0) g_topidx[b * KSEL + sel] = bi;
        if ((bi >> 2) == tid) mval[bi & 3] = -1.f;
    }
}

// ---------------------------------------------------------------------------
// Kernel 4: gather -> anchor vector -> lift (259->64) -> project (64->1024)
// ---------------------------------------------------------------------------
__global__ __launch_bounds__(256) void k_tokens(
    const float* __restrict__ x, const float* __restrict__ mu,
    const float* __restrict__ sigma, const float* __restrict__ W_lift,
    const float* __restrict__ b_lift, const float* __restrict__ W_proj,
    const float* __restrict__ b_proj, float* __restrict__ out)
{
    __shared__ float u[AD];
    __shared__ float lf[KLIFT];
    const int b = blockIdx.x, j = blockIdx.y;
    const int tid = threadIdx.x;
    const int idx = g_topidx[b * KSEL + j];

    {
        float v = x[((size_t)b * TT + idx) * DIN + tid] - g_xmean[b * DIN + tid];
        u[tid] = (v - mu[tid]) / sigma[tid];
    }
    if (tid == 0) {
        float sali = g_sal[b * TT + idx];
        float ms = g_msal[b];
        u[256] = ((sali - ms) - mu[256]) / sigma[256];
        float tn = (float)idx * (1.0f / 4096.0f);
        u[257] = ((tn - 0.4998779296875f) - mu[257]) / sigma[257];
        float ds = (idx == 0) ? 0.f : (sali - g_sal[b * TT + idx - 1]);
        float mds = (g_sal[b * TT + TT - 1] - g_sal[b * TT]) * (1.0f / 4096.0f);
        u[258] = ((ds - mds) - mu[258]) / sigma[258];
    }
    __syncthreads();

    if (tid < KLIFT) {
        float acc = b_lift[tid];
        for (int d = 0; d < AD; d++)
            acc = fmaf(u[d], W_lift[d * KLIFT + tid], acc);
        lf[tid] = acc;
    }
    __syncthreads();

    float* o = out + ((size_t)(b * KSEL + j)) * DMODEL;
    for (int m = tid; m < DMODEL; m += 256) {
        float acc = b_proj[m];
#pragma unroll
        for (int k = 0; k < KLIFT; k++)
            acc = fmaf(lf[k], W_proj[k * DMODEL + m], acc);
        o[m] = acc;
    }
}

// ---------------------------------------------------------------------------
extern "C" void kernel_launch(void* const* d_in, const int* in_sizes, int n_in,
                              void* d_out, int out_size)
{
    const float* x      = (const float*)d_in[0];
    const float* W1     = (const float*)d_in[1];
    const float* b1     = (const float*)d_in[2];
    const float* w_sal  = (const float*)d_in[5];
    const float* b_sal  = (const float*)d_in[6];
    const float* mu     = (const float*)d_in[7];
    const float* sigma  = (const float*)d_in[8];
    const float* W_lift = (const float*)d_in[9];
    const float* b_lift = (const float*)d_in[10];
    const float* W_proj = (const float*)d_in[11];
    const float* b_proj = (const float*)d_in[12];
    float* out = (float*)d_out;

    static cudaStream_t s2 = []() {
        cudaStream_t s; cudaStreamCreateWithFlags(&s, cudaStreamNonBlocking); return s;
    }();
    static cudaEvent_t evF = []() {
        cudaEvent_t e; cudaEventCreateWithFlags(&e, cudaEventDisableTiming); return e;
    }();
    static cudaEvent_t evJ = []() {
        cudaEvent_t e; cudaEventCreateWithFlags(&e, cudaEventDisableTiming); return e;
    }();

    cudaEventRecord(evF, 0);
    cudaStreamWaitEvent(s2, evF, 0);
    k_xmean_part<<<dim3(BB, 16), 256, 0, s2>>>(x);
    k_xmean_fin<<<BB, 256, 0, s2>>>();
    cudaEventRecord(evJ, s2);

    k_convert_w<<<dim3(64, 16), 32>>>(W1);
    k_gemm_part<<<dim3(4, 1024), 256>>>(x, b1, w_sal);
    k_selector<<<BB, 1024>>>(b_sal, out);

    cudaStreamWaitEvent(0, evJ, 0);
    k_tokens<<<dim3(BB, KSEL), 256>>>(x, mu, sigma, W_lift, b_lift, W_proj, b_proj, out);
}

// round 12
// speedup vs baseline: 1.0545x; 1.0545x over previous
#include <cuda_runtime.h>
#include <cuda_bf16.h>
#include <cstdint>
#include <math.h>

#define BB 32
#define TT 4096
#define DIN 256
#define HID 512
#define AD 259
#define KLIFT 64
#define DMODEL 1024
#define KSEL 32
#define PGD_STEPS 60

// ---------------- scratch (device globals; no allocation allowed) ----------
__device__ float g_sal[BB * TT];
__device__ float g_spart[4][BB * TT];        // per-N-tile partial saliency dot
__device__ float g_xpart[16 * BB * DIN];
__device__ float g_xmean[BB * DIN];
__device__ float g_msal[BB];
__device__ int   g_topidx[BB * KSEL];
// W1 pre-fragmented for mma.sync B operand: [n_tile 64][k_chunk 16][lane 32]
__device__ uint2 g_BfH[64 * 16 * 32];
__device__ uint2 g_BfL[64 * 16 * 32];

__device__ __forceinline__ uint32_t pack_bf2(__nv_bfloat16 a, __nv_bfloat16 b) {
    return (uint32_t)__bfloat16_as_ushort(a) | ((uint32_t)__bfloat16_as_ushort(b) << 16);
}

// mma.sync m16n8k16 row.col f32.bf16.bf16.f32 (portable PTX, HMMA pipe)
__device__ __forceinline__ void mma_bf16(float* d, const uint32_t* a, const uint32_t* b) {
    asm volatile(
        "mma.sync.aligned.m16n8k16.row.col.f32.bf16.bf16.f32 "
        "{%0,%1,%2,%3}, {%4,%5,%6,%7}, {%8,%9}, {%0,%1,%2,%3};"
        : "+f"(d[0]), "+f"(d[1]), "+f"(d[2]), "+f"(d[3])
        : "r"(a[0]), "r"(a[1]), "r"(a[2]), "r"(a[3]), "r"(b[0]), "r"(b[1]));
}

// ldmatrix x4: loads 4 8x8 b16 matrices; lane supplies one 16B row address.
__device__ __forceinline__ void ldsm_x4(uint32_t* r, uint32_t saddr) {
    asm volatile(
        "ldmatrix.sync.aligned.m8n8.x4.shared.b16 {%0,%1,%2,%3}, [%4];"
        : "=r"(r[0]), "=r"(r[1]), "=r"(r[2]), "=r"(r[3]) : "r"(saddr));
}

__device__ __forceinline__ uint32_t smem_u32(const void* p) {
    return (uint32_t)__cvta_generic_to_shared(p);
}
// 16B-unit swizzle: distinct banks for all STS/LDSM phases
__device__ __forceinline__ uint32_t su16(uint32_t u) { return u ^ ((u >> 3) & 1u); }

// trunc-split of a float4 into bf16 hi (2 PRMT) + lo (2 FADD-pairs + cvt.bf16x2)
__device__ __forceinline__ void split4(float4 v, uint2* hi, uint2* lo) {
    uint32_t b0 = __float_as_uint(v.x), b1 = __float_as_uint(v.y);
    uint32_t b2 = __float_as_uint(v.z), b3 = __float_as_uint(v.w);
    hi->x = __byte_perm(b0, b1, 0x7632);
    hi->y = __byte_perm(b2, b3, 0x7632);
    float l0 = v.x - __uint_as_float(b0 & 0xFFFF0000u);
    float l1 = v.y - __uint_as_float(b1 & 0xFFFF0000u);
    float l2 = v.z - __uint_as_float(b2 & 0xFFFF0000u);
    float l3 = v.w - __uint_as_float(b3 & 0xFFFF0000u);
    __nv_bfloat162 p0 = __float22bfloat162_rn(make_float2(l0, l1));
    __nv_bfloat162 p1 = __float22bfloat162_rn(make_float2(l2, l3));
    lo->x = *(uint32_t*)&p0;
    lo->y = *(uint32_t*)&p1;
}

// ---------------------------------------------------------------------------
// Kernel 0: W1 -> bf16 hi/lo (RNE) in mma B-fragment order. Coalesced via
// smem tile: 128 threads stage W1[16k x 8n] (n contiguous), warp 0 emits.
// ---------------------------------------------------------------------------
__global__ __launch_bounds__(128) void k_convert_w(const float* __restrict__ W1)
{
    __shared__ float sm[16][8];
    const int nt = blockIdx.x, kc = blockIdx.y, tid = threadIdx.x;
    sm[tid >> 3][tid & 7] =
        W1[(size_t)(kc * 16 + (tid >> 3)) * HID + nt * 8 + (tid & 7)];
    __syncthreads();
    if (tid < 32) {
        const int n = tid >> 2, kq = (tid & 3) * 2;
        float v00 = sm[kq][n],     v01 = sm[kq + 1][n];
        float v10 = sm[kq + 8][n], v11 = sm[kq + 9][n];
        __nv_bfloat16 h00 = __float2bfloat16(v00), h01 = __float2bfloat16(v01);
        __nv_bfloat16 h10 = __float2bfloat16(v10), h11 = __float2bfloat16(v11);
        __nv_bfloat16 l00 = __float2bfloat16(v00 - __bfloat162float(h00));
        __nv_bfloat16 l01 = __float2bfloat16(v01 - __bfloat162float(h01));
        __nv_bfloat16 l10 = __float2bfloat16(v10 - __bfloat162float(h10));
        __nv_bfloat16 l11 = __float2bfloat16(v11 - __bfloat162float(h11));
        const int o = (nt * 16 + kc) * 32 + tid;
        g_BfH[o] = make_uint2(pack_bf2(h00, h01), pack_bf2(h10, h11));
        g_BfL[o] = make_uint2(pack_bf2(l00, l01), pack_bf2(l10, l11));
    }
}

// ---------------------------------------------------------------------------
// Kernel 1: bf16-split GEMM via mma.sync (AhBh + AlBh + AhBl)  [R10 layout]
// m64n32 warp tile; n-fastest grid; coalesced x loads; trunc-split (PRMT);
// double-buffered smem, single barrier per mainloop iteration.
// ---------------------------------------------------------------------------
__global__ __launch_bounds__(256, 2) void k_gemm_part(
    const float* __restrict__ x, const float* __restrict__ b1,
    const float* __restrict__ w_sal)
{
    __shared__ __align__(16) unsigned char sA[2][2][4096];
    __shared__ float part[4][128];
    __shared__ float sB1[128], sWs[128];

    const int tid = threadIdx.x;
    const int n0 = blockIdx.x * 128;    // n-tile fastest: 4 CTAs share x m-tile
    const int m0 = blockIdx.y * 128;
    const int lane = tid & 31, wid = tid >> 5;
    const int wm = (wid >> 2) * 64, wn = (wid & 3) * 32;
    const int g = lane >> 2, t = lane & 3;
    const int ntbase = (n0 >> 3) + ((wid & 3) * 4);

    if (tid < 128) { sB1[tid] = b1[n0 + tid]; sWs[tid] = w_sal[n0 + tid]; }

    // coalesced A mapping: each thread owns rows arow and arow+64, seg aseg
    const int arow = tid >> 2, aseg = tid & 3;
    const uint32_t offA = su16((uint32_t)(arow * 2 + (aseg >> 1))) * 16
                        + (uint32_t)(aseg & 1) * 8;
    const uint32_t offB = su16((uint32_t)((arow + 64) * 2 + (aseg >> 1))) * 16
                        + (uint32_t)(aseg & 1) * 8;

    uint32_t frOff[4];
    {
        const int r8 = lane & 7, hr = (lane >> 3) & 1, hc = (lane >> 4) & 1;
#pragma unroll
        for (int mi = 0; mi < 4; mi++) {
            uint32_t row = (uint32_t)(wm + mi * 16 + hr * 8 + r8);
            frOff[mi] = su16(row * 2 + (uint32_t)hc) * 16;
        }
    }
    const uint32_t baseH[2] = {smem_u32(&sA[0][0][0]), smem_u32(&sA[1][0][0])};
    const uint32_t baseL[2] = {smem_u32(&sA[0][1][0]), smem_u32(&sA[1][1][0])};

    float acc[4][4][4];
#pragma unroll
    for (int mi = 0; mi < 4; mi++)
#pragma unroll
        for (int ni = 0; ni < 4; ni++)
#pragma unroll
            for (int q = 0; q < 4; q++) acc[mi][ni][q] = 0.f;

    float4 pa0, pa1;
    pa0 = *(const float4*)&x[(size_t)(m0 + arow) * DIN + aseg * 4];
    pa1 = *(const float4*)&x[(size_t)(m0 + arow + 64) * DIN + aseg * 4];

    for (int s = 0; s < 16; s++) {
        const int buf = s & 1;
        // ---- B fragments for this chunk: coalesced LDG.64 from L2 ----
        uint2 fbh[4], fbl[4];
#pragma unroll
        for (int ni = 0; ni < 4; ni++) {
            const int o = ((ntbase + ni) * 16 + s) * 32 + lane;
            fbh[ni] = g_BfH[o];
            fbl[ni] = g_BfL[o];
        }
        // ---- STS A (prefetched, trunc-split, swizzled) ----
        {
            uint2 h0, l0, h1, l1;
            split4(pa0, &h0, &l0);
            split4(pa1, &h1, &l1);
            *(uint2*)&sA[buf][0][offA] = h0;
            *(uint2*)&sA[buf][1][offA] = l0;
            *(uint2*)&sA[buf][0][offB] = h1;
            *(uint2*)&sA[buf][1][offB] = l1;
        }
        __syncthreads();   // single barrier per iteration (double buffer)
        if (s < 15) {
            pa0 = *(const float4*)&x[(size_t)(m0 + arow) * DIN + (s + 1) * 16 + aseg * 4];
            pa1 = *(const float4*)&x[(size_t)(m0 + arow + 64) * DIN + (s + 1) * 16 + aseg * 4];
        }

        uint32_t bh[4][2], bl[4][2];
#pragma unroll
        for (int ni = 0; ni < 4; ni++) {
            bh[ni][0] = fbh[ni].x; bh[ni][1] = fbh[ni].y;
            bl[ni][0] = fbl[ni].x; bl[ni][1] = fbl[ni].y;
        }
        uint32_t ah[4][4], al[4][4];
#pragma unroll
        for (int mi = 0; mi < 4; mi++) ldsm_x4(ah[mi], baseH[buf] + frOff[mi]);
#pragma unroll
        for (int mi = 0; mi < 4; mi++)
#pragma unroll
            for (int ni = 0; ni < 4; ni++)
                mma_bf16(acc[mi][ni], ah[mi], bh[ni]);
#pragma unroll
        for (int mi = 0; mi < 4; mi++)
#pragma unroll
            for (int ni = 0; ni < 4; ni++)
                mma_bf16(acc[mi][ni], ah[mi], bl[ni]);
#pragma unroll
        for (int mi = 0; mi < 4; mi++) ldsm_x4(al[mi], baseL[buf] + frOff[mi]);
#pragma unroll
        for (int mi = 0; mi < 4; mi++)
#pragma unroll
            for (int ni = 0; ni < 4; ni++)
                mma_bf16(acc[mi][ni], al[mi], bh[ni]);
    }

    // ---- epilogue: tanh + w_sal dot over this CTA's 128 columns ----
    float rsum[4][2];
#pragma unroll
    for (int mi = 0; mi < 4; mi++) { rsum[mi][0] = 0.f; rsum[mi][1] = 0.f; }
#pragma unroll
    for (int mi = 0; mi < 4; mi++)
#pragma unroll
        for (int ni = 0; ni < 4; ni++) {
            int c0 = wn + ni * 8 + t * 2;
            float w0 = sWs[c0], w1 = sWs[c0 + 1];
            float bb0 = sB1[c0], bb1 = sB1[c0 + 1];
            rsum[mi][0] += tanhf(acc[mi][ni][0] + bb0) * w0
                         + tanhf(acc[mi][ni][1] + bb1) * w1;
            rsum[mi][1] += tanhf(acc[mi][ni][2] + bb0) * w0
                         + tanhf(acc[mi][ni][3] + bb1) * w1;
        }
#pragma unroll
    for (int mi = 0; mi < 4; mi++)
#pragma unroll
        for (int sel = 0; sel < 2; sel++) {
            float v = rsum[mi][sel];
            v += __shfl_xor_sync(0xffffffffu, v, 1);
            v += __shfl_xor_sync(0xffffffffu, v, 2);
            if (t == 0) part[wid & 3][wm + mi * 16 + sel * 8 + g] = v;
        }
    __syncthreads();
    if (tid < 128) {
        float v = ((part[0][tid] + part[1][tid]) + part[2][tid]) + part[3][tid];
        g_spart[blockIdx.x][m0 + tid] = v;
    }
}

// ---------------------------------------------------------------------------
// Kernel 2a/2b: mean of x over T per batch (deterministic two-stage)
// ---------------------------------------------------------------------------
__global__ void k_xmean_part(const float* __restrict__ x)
{
    int b = blockIdx.x, ch = blockIdx.y, d = threadIdx.x;
    const float* base = x + ((size_t)b * TT + ch * 256) * DIN + d;
    float acc = 0.f;
    for (int t = 0; t < 256; t++) acc += base[(size_t)t * DIN];
    g_xpart[(ch * BB + b) * DIN + d] = acc;
}
__global__ void k_xmean_fin()
{
    int b = blockIdx.x, d = threadIdx.x;
    float acc = 0.f;
    for (int ch = 0; ch < 16; ch++) acc += g_xpart[(ch * BB + b) * DIN + d];
    g_xmean[b * DIN + d] = acc * (1.0f / TT);
}

// ---------------------------------------------------------------------------
// Kernel 3: fused sal-finalize + PGD selector.
// z-publication: buffers hold pre-projection z; neighbors reconstruct
// y = clip(z - tau_prev) locally (tau uniform). Removes the end-of-step
// barrier — each step's >=1 Newton barrier provides the ordering.
// ---------------------------------------------------------------------------
__global__ __launch_bounds__(1024) void k_selector(
    const float* __restrict__ b_sal, float* __restrict__ d_out)
{
    __shared__ float zsA[TT];
    __shared__ float zsB[TT];
    __shared__ float redS[2][32], redC[2][32];
    __shared__ float redT[2][32];
    __shared__ int   redi[2][32];

    const int b = blockIdx.x;
    const int tid = threadIdx.x;
    const int lane = tid & 31, wid = tid >> 5;
    const int i0 = tid * 4;

    float4 p0 = *(const float4*)&g_spart[0][b * TT + i0];
    float4 p1 = *(const float4*)&g_spart[1][b * TT + i0];
    float4 p2 = *(const float4*)&g_spart[2][b * TT + i0];
    float4 p3 = *(const float4*)&g_spart[3][b * TT + i0];
    const float bs = b_sal[0];
    float s[4];
    {
        float z0 = ((p0.x + p1.x) + p2.x) + p3.x + bs;
        float z1 = ((p0.y + p1.y) + p2.y) + p3.y + bs;
        float z2 = ((p0.z + p1.z) + p2.z) + p3.z + bs;
        float z3 = ((p0.w + p1.w) + p2.w) + p3.w + bs;
        s[0] = fmaxf(z0, 0.f) + log1pf(expf(-fabsf(z0)));
        s[1] = fmaxf(z1, 0.f) + log1pf(expf(-fabsf(z1)));
        s[2] = fmaxf(z2, 0.f) + log1pf(expf(-fabsf(z2)));
        s[3] = fmaxf(z3, 0.f) + log1pf(expf(-fabsf(z3)));
    }
    *(float4*)&g_sal[b * TT + i0] = make_float4(s[0], s[1], s[2], s[3]);

    float y[4] = {0.0078125f, 0.0078125f, 0.0078125f, 0.0078125f};
    // initial buffer holds y0 as "z" with tau_prev = 0 (clip(y0-0)=y0)
    zsA[i0] = y[0]; zsA[i0 + 1] = y[1]; zsA[i0 + 2] = y[2]; zsA[i0 + 3] = y[3];
    __syncthreads();

    float tau_prev = 0.f;
    for (int step = 0; step < PGD_STEPS; step++) {
        const float* rd = (step & 1) ? zsB : zsA;
        float*       wr = (step & 1) ? zsA : zsB;
        // neighbor y = clip(z_neighbor - tau_prev); identical expression to own y
        float l1 = (i0 > 0) ? fminf(fmaxf(rd[i0 - 1] - tau_prev, 0.f), 1.f) : 0.f;
        float l2 = (i0 > 0) ? fminf(fmaxf(rd[i0 - 2] - tau_prev, 0.f), 1.f) : 0.f;
        float r1 = (i0 + 4 < TT) ? fminf(fmaxf(rd[i0 + 4] - tau_prev, 0.f), 1.f) : 0.f;
        float r2 = (i0 + 4 < TT) ? fminf(fmaxf(rd[i0 + 5] - tau_prev, 0.f), 1.f) : 0.f;
        float nb[4];
        nb[0] = ((y[1] + l1) + y[2]) + l2;
        nb[1] = ((y[2] + y[0]) + y[3]) + l1;
        nb[2] = ((y[3] + y[1]) + r1) + y[0];
        nb[3] = ((r1 + y[2]) + r2) + y[1];

        float z[4];
#pragma unroll
        for (int q = 0; q < 4; q++) {
            float g = (s[q] - y[q]) - 0.5f * nb[q];
            z[q] = fminf(fmaxf(y[q] + 0.1f * g, 0.f), 1.f);
        }
        // publish z now; ordering provided by >=1 Newton barrier below
        wr[i0] = z[0]; wr[i0 + 1] = z[1]; wr[i0 + 2] = z[2]; wr[i0 + 3] = z[3];

        float tau = tau_prev;
        for (int it = 0; it < 24; it++) {
            const int p = it & 1;
            float ls = 0.f, lc = 0.f;
#pragma unroll
            for (int q = 0; q < 4; q++)
                if (z[q] > tau) { ls += z[q]; lc += 1.f; }
#pragma unroll
            for (int o = 16; o; o >>= 1) {
                ls += __shfl_xor_sync(0xffffffffu, ls, o);
                lc += __shfl_xor_sync(0xffffffffu, lc, o);
            }
            if (lane == 0) { redS[p][wid] = ls; redC[p][wid] = lc; }
            __syncthreads();
            float S = redS[p][lane], C = redC[p][lane];
#pragma unroll
            for (int o = 16; o; o >>= 1) {
                S += __shfl_xor_sync(0xffffffffu, S, o);
                C += __shfl_xor_sync(0xffffffffu, C, o);
            }
            float tnew = (C >= 1.f) ? fmaxf((S - 32.f) / C, 0.f) : 0.f;
            if (tnew == tau) break;     // uniform decision
            tau = tnew;
        }
        tau_prev = tau;
#pragma unroll
        for (int q = 0; q < 4; q++)
            y[q] = fminf(fmaxf(z[q] - tau, 0.f), 1.f);
        // no end-of-step barrier
    }
    __syncthreads();   // protect redS/redT reuse below vs last Newton reads

    float* outY = d_out + (size_t)BB * KSEL * DMODEL + (size_t)b * TT;
    *(float4*)&outY[i0] = make_float4(y[0], y[1], y[2], y[3]);

    {
        float ms = ((s[0] + s[1]) + s[2]) + s[3];
#pragma unroll
        for (int o = 16; o; o >>= 1) ms += __shfl_xor_sync(0xffffffffu, ms, o);
        if (lane == 0) redS[0][wid] = ms;
        __syncthreads();
        if (tid < 32) {
            float v = redS[0][lane];
#pragma unroll
            for (int o = 16; o; o >>= 1) v += __shfl_xor_sync(0xffffffffu, v, o);
            if (lane == 0) g_msal[b] = v * (1.0f / TT);
        }
        __syncthreads();
    }

    float mval[4] = {y[0], y[1], y[2], y[3]};
    for (int sel = 0; sel < KSEL; sel++) {
        const int p = sel & 1;
        float bv = -1.f; int bi = TT;
#pragma unroll
        for (int q = 0; q < 4; q++)
            if (mval[q] > bv) { bv = mval[q]; bi = i0 + q; }
#pragma unroll
        for (int o = 16; o; o >>= 1) {
            float ov = __shfl_xor_sync(0xffffffffu, bv, o);
            int   oi = __shfl_xor_sync(0xffffffffu, bi, o);
            if (ov > bv || (ov == bv && oi < bi)) { bv = ov; bi = oi; }
        }
        if (lane == 0) { redT[p][wid] = bv; redi[p][wid] = bi; }
        __syncthreads();
        bv = redT[p][lane]; bi = redi[p][lane];
#pragma unroll
        for (int o = 16; o; o >>= 1) {
            float ov = __shfl_xor_sync(0xffffffffu, bv, o);
            int   oi = __shfl_xor_sync(0xffffffffu, bi, o);
            if (ov > bv || (ov == bv && oi < bi)) { bv = ov; bi = oi; }
        }
        if (tid == 0) g_topidx[b * KSEL + sel] = bi;
        if ((bi >> 2) == tid) mval[bi & 3] = -1.f;
    }
}

// ---------------------------------------------------------------------------
// Kernel 4: gather -> anchor vector -> lift (259->64) -> project (64->1024)
// ---------------------------------------------------------------------------
__global__ __launch_bounds__(256) void k_tokens(
    const float* __restrict__ x, const float* __restrict__ mu,
    const float* __restrict__ sigma, const float* __restrict__ W_lift,
    const float* __restrict__ b_lift, const float* __restrict__ W_proj,
    const float* __restrict__ b_proj, float* __restrict__ out)
{
    __shared__ float u[AD];
    __shared__ float lf[KLIFT];
    const int b = blockIdx.x, j = blockIdx.y;
    const int tid = threadIdx.x;
    const int idx = g_topidx[b * KSEL + j];

    {
        float v = x[((size_t)b * TT + idx) * DIN + tid] - g_xmean[b * DIN + tid];
        u[tid] = (v - mu[tid]) / sigma[tid];
    }
    if (tid == 0) {
        float sali = g_sal[b * TT + idx];
        float ms = g_msal[b];
        u[256] = ((sali - ms) - mu[256]) / sigma[256];
        float tn = (float)idx * (1.0f / 4096.0f);
        u[257] = ((tn - 0.4998779296875f) - mu[257]) / sigma[257];
        float ds = (idx == 0) ? 0.f : (sali - g_sal[b * TT + idx - 1]);
        float mds = (g_sal[b * TT + TT - 1] - g_sal[b * TT]) * (1.0f / 4096.0f);
        u[258] = ((ds - mds) - mu[258]) / sigma[258];
    }
    __syncthreads();

    if (tid < KLIFT) {
        float acc = b_lift[tid];
        for (int d = 0; d < AD; d++)
            acc = fmaf(u[d], W_lift[d * KLIFT + tid], acc);
        lf[tid] = acc;
    }
    __syncthreads();

    float* o = out + ((size_t)(b * KSEL + j)) * DMODEL;
    for (int m = tid; m < DMODEL; m += 256) {
        float acc = b_proj[m];
#pragma unroll
        for (int k = 0; k < KLIFT; k++)
            acc = fmaf(lf[k], W_proj[k * DMODEL + m], acc);
        o[m] = acc;
    }
}

// ---------------------------------------------------------------------------
extern "C" void kernel_launch(void* const* d_in, const int* in_sizes, int n_in,
                              void* d_out, int out_size)
{
    const float* x      = (const float*)d_in[0];
    const float* W1     = (const float*)d_in[1];
    const float* b1     = (const float*)d_in[2];
    const float* w_sal  = (const float*)d_in[5];
    const float* b_sal  = (const float*)d_in[6];
    const float* mu     = (const float*)d_in[7];
    const float* sigma  = (const float*)d_in[8];
    const float* W_lift = (const float*)d_in[9];
    const float* b_lift = (const float*)d_in[10];
    const float* W_proj = (const float*)d_in[11];
    const float* b_proj = (const float*)d_in[12];
    float* out = (float*)d_out;

    static cudaStream_t s2 = []() {
        cudaStream_t s; cudaStreamCreateWithFlags(&s, cudaStreamNonBlocking); return s;
    }();
    static cudaEvent_t evF = []() {
        cudaEvent_t e; cudaEventCreateWithFlags(&e, cudaEventDisableTiming); return e;
    }();
    static cudaEvent_t evJ = []() {
        cudaEvent_t e; cudaEventCreateWithFlags(&e, cudaEventDisableTiming); return e;
    }();

    cudaEventRecord(evF, 0);
    cudaStreamWaitEvent(s2, evF, 0);
    k_xmean_part<<<dim3(BB, 16), 256, 0, s2>>>(x);
    k_xmean_fin<<<BB, 256, 0, s2>>>();
    cudaEventRecord(evJ, s2);

    k_convert_w<<<dim3(64, 16), 128>>>(W1);
    k_gemm_part<<<dim3(4, 1024), 256>>>(x, b1, w_sal);
    k_selector<<<BB, 1024>>>(b_sal, out);

    cudaStreamWaitEvent(0, evJ, 0);
    k_tokens<<<dim3(BB, KSEL), 256>>>(x, mu, sigma, W_lift, b_lift, W_proj, b_proj, out);
}

// round 13
// speedup vs baseline: 1.1321x; 1.0737x over previous
#include <cuda_runtime.h>
#include <cuda_bf16.h>
#include <cstdint>
#include <math.h>

#define BB 32
#define TT 4096
#define DIN 256
#define HID 512
#define AD 259
#define KLIFT 64
#define DMODEL 1024
#define KSEL 32
#define PGD_STEPS 60

// ---------------- scratch (device globals; no allocation allowed) ----------
__device__ float g_sal[BB * TT];
__device__ float g_spart[4][BB * TT];        // per-N-tile partial saliency dot
__device__ float g_xpart[16 * BB * DIN];
__device__ float g_xmean[BB * DIN];
__device__ float g_msal[BB];
__device__ int   g_topidx[BB * KSEL];
__device__ float g_cloud[BB * KSEL * KLIFT];
// W1 pre-fragmented for mma.sync B operand: [n_tile 64][k_chunk 16][lane 32]
__device__ uint2 g_BfH[64 * 16 * 32];
__device__ uint2 g_BfL[64 * 16 * 32];

__device__ __forceinline__ uint32_t pack_bf2(__nv_bfloat16 a, __nv_bfloat16 b) {
    return (uint32_t)__bfloat16_as_ushort(a) | ((uint32_t)__bfloat16_as_ushort(b) << 16);
}

// mma.sync m16n8k16 row.col f32.bf16.bf16.f32 (portable PTX, HMMA pipe)
__device__ __forceinline__ void mma_bf16(float* d, const uint32_t* a, const uint32_t* b) {
    asm volatile(
        "mma.sync.aligned.m16n8k16.row.col.f32.bf16.bf16.f32 "
        "{%0,%1,%2,%3}, {%4,%5,%6,%7}, {%8,%9}, {%0,%1,%2,%3};"
        : "+f"(d[0]), "+f"(d[1]), "+f"(d[2]), "+f"(d[3])
        : "r"(a[0]), "r"(a[1]), "r"(a[2]), "r"(a[3]), "r"(b[0]), "r"(b[1]));
}

// ldmatrix x4: loads 4 8x8 b16 matrices; lane supplies one 16B row address.
__device__ __forceinline__ void ldsm_x4(uint32_t* r, uint32_t saddr) {
    asm volatile(
        "ldmatrix.sync.aligned.m8n8.x4.shared.b16 {%0,%1,%2,%3}, [%4];"
        : "=r"(r[0]), "=r"(r[1]), "=r"(r[2]), "=r"(r[3]) : "r"(saddr));
}

__device__ __forceinline__ uint32_t smem_u32(const void* p) {
    return (uint32_t)__cvta_generic_to_shared(p);
}
// 16B-unit swizzle: distinct banks for all STS/LDSM phases
__device__ __forceinline__ uint32_t su16(uint32_t u) { return u ^ ((u >> 3) & 1u); }

// trunc-split of a float4 into bf16 hi (2 PRMT) + lo (2 FADD-pairs + cvt.bf16x2)
__device__ __forceinline__ void split4(float4 v, uint2* hi, uint2* lo) {
    uint32_t b0 = __float_as_uint(v.x), b1 = __float_as_uint(v.y);
    uint32_t b2 = __float_as_uint(v.z), b3 = __float_as_uint(v.w);
    hi->x = __byte_perm(b0, b1, 0x7632);
    hi->y = __byte_perm(b2, b3, 0x7632);
    float l0 = v.x - __uint_as_float(b0 & 0xFFFF0000u);
    float l1 = v.y - __uint_as_float(b1 & 0xFFFF0000u);
    float l2 = v.z - __uint_as_float(b2 & 0xFFFF0000u);
    float l3 = v.w - __uint_as_float(b3 & 0xFFFF0000u);
    __nv_bfloat162 p0 = __float22bfloat162_rn(make_float2(l0, l1));
    __nv_bfloat162 p1 = __float22bfloat162_rn(make_float2(l2, l3));
    lo->x = *(uint32_t*)&p0;
    lo->y = *(uint32_t*)&p1;
}

// ---------------------------------------------------------------------------
// Kernel 0: W1 -> bf16 hi/lo (RNE) in mma B-fragment order (coalesced stage).
// ---------------------------------------------------------------------------
__global__ __launch_bounds__(128) void k_convert_w(const float* __restrict__ W1)
{
    __shared__ float sm[16][8];
    const int nt = blockIdx.x, kc = blockIdx.y, tid = threadIdx.x;
    sm[tid >> 3][tid & 7] =
        W1[(size_t)(kc * 16 + (tid >> 3)) * HID + nt * 8 + (tid & 7)];
    __syncthreads();
    if (tid < 32) {
        const int n = tid >> 2, kq = (tid & 3) * 2;
        float v00 = sm[kq][n],     v01 = sm[kq + 1][n];
        float v10 = sm[kq + 8][n], v11 = sm[kq + 9][n];
        __nv_bfloat16 h00 = __float2bfloat16(v00), h01 = __float2bfloat16(v01);
        __nv_bfloat16 h10 = __float2bfloat16(v10), h11 = __float2bfloat16(v11);
        __nv_bfloat16 l00 = __float2bfloat16(v00 - __bfloat162float(h00));
        __nv_bfloat16 l01 = __float2bfloat16(v01 - __bfloat162float(h01));
        __nv_bfloat16 l10 = __float2bfloat16(v10 - __bfloat162float(h10));
        __nv_bfloat16 l11 = __float2bfloat16(v11 - __bfloat162float(h11));
        const int o = (nt * 16 + kc) * 32 + tid;
        g_BfH[o] = make_uint2(pack_bf2(h00, h01), pack_bf2(h10, h11));
        g_BfL[o] = make_uint2(pack_bf2(l00, l01), pack_bf2(l10, l11));
    }
}

// ---------------------------------------------------------------------------
// Kernel 1: bf16-split GEMM via mma.sync (AhBh + AlBh + AhBl)  [R10 layout]
// ---------------------------------------------------------------------------
__global__ __launch_bounds__(256, 2) void k_gemm_part(
    const float* __restrict__ x, const float* __restrict__ b1,
    const float* __restrict__ w_sal)
{
    __shared__ __align__(16) unsigned char sA[2][2][4096];
    __shared__ float part[4][128];
    __shared__ float sB1[128], sWs[128];

    const int tid = threadIdx.x;
    const int n0 = blockIdx.x * 128;
    const int m0 = blockIdx.y * 128;
    const int lane = tid & 31, wid = tid >> 5;
    const int wm = (wid >> 2) * 64, wn = (wid & 3) * 32;
    const int g = lane >> 2, t = lane & 3;
    const int ntbase = (n0 >> 3) + ((wid & 3) * 4);

    if (tid < 128) { sB1[tid] = b1[n0 + tid]; sWs[tid] = w_sal[n0 + tid]; }

    const int arow = tid >> 2, aseg = tid & 3;
    const uint32_t offA = su16((uint32_t)(arow * 2 + (aseg >> 1))) * 16
                        + (uint32_t)(aseg & 1) * 8;
    const uint32_t offB = su16((uint32_t)((arow + 64) * 2 + (aseg >> 1))) * 16
                        + (uint32_t)(aseg & 1) * 8;

    uint32_t frOff[4];
    {
        const int r8 = lane & 7, hr = (lane >> 3) & 1, hc = (lane >> 4) & 1;
#pragma unroll
        for (int mi = 0; mi < 4; mi++) {
            uint32_t row = (uint32_t)(wm + mi * 16 + hr * 8 + r8);
            frOff[mi] = su16(row * 2 + (uint32_t)hc) * 16;
        }
    }
    const uint32_t baseH[2] = {smem_u32(&sA[0][0][0]), smem_u32(&sA[1][0][0])};
    const uint32_t baseL[2] = {smem_u32(&sA[0][1][0]), smem_u32(&sA[1][1][0])};

    float acc[4][4][4];
#pragma unroll
    for (int mi = 0; mi < 4; mi++)
#pragma unroll
        for (int ni = 0; ni < 4; ni++)
#pragma unroll
            for (int q = 0; q < 4; q++) acc[mi][ni][q] = 0.f;

    float4 pa0, pa1;
    pa0 = *(const float4*)&x[(size_t)(m0 + arow) * DIN + aseg * 4];
    pa1 = *(const float4*)&x[(size_t)(m0 + arow + 64) * DIN + aseg * 4];

    for (int s = 0; s < 16; s++) {
        const int buf = s & 1;
        uint2 fbh[4], fbl[4];
#pragma unroll
        for (int ni = 0; ni < 4; ni++) {
            const int o = ((ntbase + ni) * 16 + s) * 32 + lane;
            fbh[ni] = g_BfH[o];
            fbl[ni] = g_BfL[o];
        }
        {
            uint2 h0, l0, h1, l1;
            split4(pa0, &h0, &l0);
            split4(pa1, &h1, &l1);
            *(uint2*)&sA[buf][0][offA] = h0;
            *(uint2*)&sA[buf][1][offA] = l0;
            *(uint2*)&sA[buf][0][offB] = h1;
            *(uint2*)&sA[buf][1][offB] = l1;
        }
        __syncthreads();
        if (s < 15) {
            pa0 = *(const float4*)&x[(size_t)(m0 + arow) * DIN + (s + 1) * 16 + aseg * 4];
            pa1 = *(const float4*)&x[(size_t)(m0 + arow + 64) * DIN + (s + 1) * 16 + aseg * 4];
        }

        uint32_t bh[4][2], bl[4][2];
#pragma unroll
        for (int ni = 0; ni < 4; ni++) {
            bh[ni][0] = fbh[ni].x; bh[ni][1] = fbh[ni].y;
            bl[ni][0] = fbl[ni].x; bl[ni][1] = fbl[ni].y;
        }
        uint32_t ah[4][4], al[4][4];
#pragma unroll
        for (int mi = 0; mi < 4; mi++) ldsm_x4(ah[mi], baseH[buf] + frOff[mi]);
#pragma unroll
        for (int mi = 0; mi < 4; mi++)
#pragma unroll
            for (int ni = 0; ni < 4; ni++)
                mma_bf16(acc[mi][ni], ah[mi], bh[ni]);
#pragma unroll
        for (int mi = 0; mi < 4; mi++)
#pragma unroll
            for (int ni = 0; ni < 4; ni++)
                mma_bf16(acc[mi][ni], ah[mi], bl[ni]);
#pragma unroll
        for (int mi = 0; mi < 4; mi++) ldsm_x4(al[mi], baseL[buf] + frOff[mi]);
#pragma unroll
        for (int mi = 0; mi < 4; mi++)
#pragma unroll
            for (int ni = 0; ni < 4; ni++)
                mma_bf16(acc[mi][ni], al[mi], bh[ni]);
    }

    float rsum[4][2];
#pragma unroll
    for (int mi = 0; mi < 4; mi++) { rsum[mi][0] = 0.f; rsum[mi][1] = 0.f; }
#pragma unroll
    for (int mi = 0; mi < 4; mi++)
#pragma unroll
        for (int ni = 0; ni < 4; ni++) {
            int c0 = wn + ni * 8 + t * 2;
            float w0 = sWs[c0], w1 = sWs[c0 + 1];
            float bb0 = sB1[c0], bb1 = sB1[c0 + 1];
            rsum[mi][0] += tanhf(acc[mi][ni][0] + bb0) * w0
                         + tanhf(acc[mi][ni][1] + bb1) * w1;
            rsum[mi][1] += tanhf(acc[mi][ni][2] + bb0) * w0
                         + tanhf(acc[mi][ni][3] + bb1) * w1;
        }
#pragma unroll
    for (int mi = 0; mi < 4; mi++)
#pragma unroll
        for (int sel = 0; sel < 2; sel++) {
            float v = rsum[mi][sel];
            v += __shfl_xor_sync(0xffffffffu, v, 1);
            v += __shfl_xor_sync(0xffffffffu, v, 2);
            if (t == 0) part[wid & 3][wm + mi * 16 + sel * 8 + g] = v;
        }
    __syncthreads();
    if (tid < 128) {
        float v = ((part[0][tid] + part[1][tid]) + part[2][tid]) + part[3][tid];
        g_spart[blockIdx.x][m0 + tid] = v;
    }
}

// ---------------------------------------------------------------------------
// Kernel 2a/2b: mean of x over T per batch (deterministic two-stage)
// ---------------------------------------------------------------------------
__global__ void k_xmean_part(const float* __restrict__ x)
{
    int b = blockIdx.x, ch = blockIdx.y, d = threadIdx.x;
    const float* base = x + ((size_t)b * TT + ch * 256) * DIN + d;
    float acc = 0.f;
    for (int t = 0; t < 256; t++) acc += base[(size_t)t * DIN];
    g_xpart[(ch * BB + b) * DIN + d] = acc;
}
__global__ void k_xmean_fin()
{
    int b = blockIdx.x, d = threadIdx.x;
    float acc = 0.f;
    for (int ch = 0; ch < 16; ch++) acc += g_xpart[(ch * BB + b) * DIN + d];
    g_xmean[b * DIN + d] = acc * (1.0f / TT);
}

// ---------------------------------------------------------------------------
// Kernel 3: fused sal-finalize + PGD selector.
// Newton with EPSILON break (|d tau| <= 1e-6, cap 12) — exact-equality break
// can 2-cycle oscillate in FP and burn all 24 iterations.
// ---------------------------------------------------------------------------
__global__ __launch_bounds__(1024) void k_selector(
    const float* __restrict__ b_sal, float* __restrict__ d_out)
{
    __shared__ float zsA[TT];
    __shared__ float zsB[TT];
    __shared__ float redS[2][32], redC[2][32];
    __shared__ float redT[2][32];
    __shared__ int   redi[2][32];

    const int b = blockIdx.x;
    const int tid = threadIdx.x;
    const int lane = tid & 31, wid = tid >> 5;
    const int i0 = tid * 4;

    float4 p0 = *(const float4*)&g_spart[0][b * TT + i0];
    float4 p1 = *(const float4*)&g_spart[1][b * TT + i0];
    float4 p2 = *(const float4*)&g_spart[2][b * TT + i0];
    float4 p3 = *(const float4*)&g_spart[3][b * TT + i0];
    const float bs = b_sal[0];
    float s[4];
    {
        float z0 = ((p0.x + p1.x) + p2.x) + p3.x + bs;
        float z1 = ((p0.y + p1.y) + p2.y) + p3.y + bs;
        float z2 = ((p0.z + p1.z) + p2.z) + p3.z + bs;
        float z3 = ((p0.w + p1.w) + p2.w) + p3.w + bs;
        s[0] = fmaxf(z0, 0.f) + log1pf(expf(-fabsf(z0)));
        s[1] = fmaxf(z1, 0.f) + log1pf(expf(-fabsf(z1)));
        s[2] = fmaxf(z2, 0.f) + log1pf(expf(-fabsf(z2)));
        s[3] = fmaxf(z3, 0.f) + log1pf(expf(-fabsf(z3)));
    }
    *(float4*)&g_sal[b * TT + i0] = make_float4(s[0], s[1], s[2], s[3]);

    float y[4] = {0.0078125f, 0.0078125f, 0.0078125f, 0.0078125f};
    zsA[i0] = y[0]; zsA[i0 + 1] = y[1]; zsA[i0 + 2] = y[2]; zsA[i0 + 3] = y[3];
    __syncthreads();

    float tau_prev = 0.f;
    for (int step = 0; step < PGD_STEPS; step++) {
        const float* rd = (step & 1) ? zsB : zsA;
        float*       wr = (step & 1) ? zsA : zsB;
        float l1 = (i0 > 0) ? fminf(fmaxf(rd[i0 - 1] - tau_prev, 0.f), 1.f) : 0.f;
        float l2 = (i0 > 0) ? fminf(fmaxf(rd[i0 - 2] - tau_prev, 0.f), 1.f) : 0.f;
        float r1 = (i0 + 4 < TT) ? fminf(fmaxf(rd[i0 + 4] - tau_prev, 0.f), 1.f) : 0.f;
        float r2 = (i0 + 4 < TT) ? fminf(fmaxf(rd[i0 + 5] - tau_prev, 0.f), 1.f) : 0.f;
        float nb[4];
        nb[0] = ((y[1] + l1) + y[2]) + l2;
        nb[1] = ((y[2] + y[0]) + y[3]) + l1;
        nb[2] = ((y[3] + y[1]) + r1) + y[0];
        nb[3] = ((r1 + y[2]) + r2) + y[1];

        float z[4];
#pragma unroll
        for (int q = 0; q < 4; q++) {
            float g = (s[q] - y[q]) - 0.5f * nb[q];
            z[q] = fminf(fmaxf(y[q] + 0.1f * g, 0.f), 1.f);
        }
        wr[i0] = z[0]; wr[i0 + 1] = z[1]; wr[i0 + 2] = z[2]; wr[i0 + 3] = z[3];

        float tau = tau_prev;
        for (int it = 0; it < 12; it++) {
            const int p = it & 1;
            float ls = 0.f, lc = 0.f;
#pragma unroll
            for (int q = 0; q < 4; q++)
                if (z[q] > tau) { ls += z[q]; lc += 1.f; }
#pragma unroll
            for (int o = 16; o; o >>= 1) {
                ls += __shfl_xor_sync(0xffffffffu, ls, o);
                lc += __shfl_xor_sync(0xffffffffu, lc, o);
            }
            if (lane == 0) { redS[p][wid] = ls; redC[p][wid] = lc; }
            __syncthreads();
            float S = redS[p][lane], C = redC[p][lane];
#pragma unroll
            for (int o = 16; o; o >>= 1) {
                S += __shfl_xor_sync(0xffffffffu, S, o);
                C += __shfl_xor_sync(0xffffffffu, C, o);
            }
            float tnew = (C >= 1.f) ? fmaxf((S - 32.f) / C, 0.f) : 0.f;
            if (fabsf(tnew - tau) <= 1e-6f) { tau = tnew; break; }  // uniform
            tau = tnew;
        }
        tau_prev = tau;
#pragma unroll
        for (int q = 0; q < 4; q++)
            y[q] = fminf(fmaxf(z[q] - tau, 0.f), 1.f);
    }
    __syncthreads();

    float* outY = d_out + (size_t)BB * KSEL * DMODEL + (size_t)b * TT;
    *(float4*)&outY[i0] = make_float4(y[0], y[1], y[2], y[3]);

    {
        float ms = ((s[0] + s[1]) + s[2]) + s[3];
#pragma unroll
        for (int o = 16; o; o >>= 1) ms += __shfl_xor_sync(0xffffffffu, ms, o);
        if (lane == 0) redS[0][wid] = ms;
        __syncthreads();
        if (tid < 32) {
            float v = redS[0][lane];
#pragma unroll
            for (int o = 16; o; o >>= 1) v += __shfl_xor_sync(0xffffffffu, v, o);
            if (lane == 0) g_msal[b] = v * (1.0f / TT);
        }
        __syncthreads();
    }

    float mval[4] = {y[0], y[1], y[2], y[3]};
    for (int sel = 0; sel < KSEL; sel++) {
        const int p = sel & 1;
        float bv = -1.f; int bi = TT;
#pragma unroll
        for (int q = 0; q < 4; q++)
            if (mval[q] > bv) { bv = mval[q]; bi = i0 + q; }
#pragma unroll
        for (int o = 16; o; o >>= 1) {
            float ov = __shfl_xor_sync(0xffffffffu, bv, o);
            int   oi = __shfl_xor_sync(0xffffffffu, bi, o);
            if (ov > bv || (ov == bv && oi < bi)) { bv = ov; bi = oi; }
        }
        if (lane == 0) { redT[p][wid] = bv; redi[p][wid] = bi; }
        __syncthreads();
        bv = redT[p][lane]; bi = redi[p][lane];
#pragma unroll
        for (int o = 16; o; o >>= 1) {
            float ov = __shfl_xor_sync(0xffffffffu, bv, o);
            int   oi = __shfl_xor_sync(0xffffffffu, bi, o);
            if (ov > bv || (ov == bv && oi < bi)) { bv = ov; bi = oi; }
        }
        if (tid == 0) g_topidx[b * KSEL + sel] = bi;
        if ((bi >> 2) == tid) mval[bi & 3] = -1.f;
    }
}

// ---------------------------------------------------------------------------
// Kernel 4a: gather + anchor vector + lift (259->64) -> g_cloud
// 256 threads: 64 outputs x 4 partial segments (deterministic combine).
// ---------------------------------------------------------------------------
__global__ __launch_bounds__(256) void k_lift(
    const float* __restrict__ x, const float* __restrict__ mu,
    const float* __restrict__ sigma, const float* __restrict__ W_lift,
    const float* __restrict__ b_lift)
{
    __shared__ float u[AD];
    __shared__ float partl[4][KLIFT];
    const int b = blockIdx.x, j = blockIdx.y;
    const int tid = threadIdx.x;
    const int idx = g_topidx[b * KSEL + j];

    {
        float v = x[((size_t)b * TT + idx) * DIN + tid] - g_xmean[b * DIN + tid];
        u[tid] = (v - mu[tid]) / sigma[tid];
    }
    if (tid == 0) {
        float sali = g_sal[b * TT + idx];
        float ms = g_msal[b];
        u[256] = ((sali - ms) - mu[256]) / sigma[256];
        float tn = (float)idx * (1.0f / 4096.0f);
        u[257] = ((tn - 0.4998779296875f) - mu[257]) / sigma[257];
        float ds = (idx == 0) ? 0.f : (sali - g_sal[b * TT + idx - 1]);
        float mds = (g_sal[b * TT + TT - 1] - g_sal[b * TT]) * (1.0f / 4096.0f);
        u[258] = ((ds - mds) - mu[258]) / sigma[258];
    }
    __syncthreads();

    {
        const int kk = tid & 63, pp = tid >> 6;          // 4 segments of 65/65/65/64
        const int d0 = pp * 65;
        const int d1 = (pp == 3) ? AD : d0 + 65;
        float acc = 0.f;
        for (int d = d0; d < d1; d++)
            acc = fmaf(u[d], W_lift[d * KLIFT + kk], acc);
        partl[pp][kk] = acc;
    }
    __syncthreads();
    if (tid < KLIFT) {
        float v = b_lift[tid]
                + (((partl[0][tid] + partl[1][tid]) + partl[2][tid]) + partl[3][tid]);
        g_cloud[(b * KSEL + j) * KLIFT + tid] = v;
    }
}

// ---------------------------------------------------------------------------
// Kernel 4b: tokens = cloud[b,32,64] @ W_proj[64,1024] + b_proj
// grid (32 batches, 8 n-blocks of 128). W_proj tile staged in smem (reused
// by all 32 rows) -> total W_proj L2 traffic 8MB instead of 268MB.
// ---------------------------------------------------------------------------
__global__ __launch_bounds__(256) void k_proj(
    const float* __restrict__ W_proj, const float* __restrict__ b_proj,
    float* __restrict__ out)
{
    __shared__ float sW[KLIFT][128];
    __shared__ float sC[KSEL][KLIFT];
    const int b = blockIdx.x, n0 = blockIdx.y * 128;
    const int tid = threadIdx.x;

    // stage W_proj tile [64 x 128] coalesced: 8192 floats / 256 = 32 each
#pragma unroll
    for (int it = 0; it < 8; it++) {
        int i = tid + it * 256;            // float4 index over 64x32 float4s
        int k = i >> 5, c4 = i & 31;
        *(float4*)&sW[k][c4 * 4] =
            *(const float4*)&W_proj[(size_t)k * DMODEL + n0 + c4 * 4];
    }
    // stage cloud rows [32 x 64]
#pragma unroll
    for (int it = 0; it < 2; it++) {
        int i = tid + it * 256;            // float4 index over 32x16 float4s
        int r = i >> 4, c4 = i & 15;
        *(float4*)&sC[r][c4 * 4] =
            *(const float4*)&g_cloud[(b * KSEL + r) * KLIFT + c4 * 4];
    }
    __syncthreads();

    const int r = tid >> 3;                // 0..31
    const int c0 = (tid & 7) * 16;         // 16 cols per thread
    float4 acc[4];
#pragma unroll
    for (int i = 0; i < 4; i++)
        acc[i] = *(const float4*)&b_proj[n0 + c0 + i * 4];
#pragma unroll
    for (int k = 0; k < KLIFT; k++) {
        float a = sC[r][k];
#pragma unroll
        for (int i = 0; i < 4; i++) {
            float4 w = *(const float4*)&sW[k][c0 + i * 4];
            acc[i].x = fmaf(a, w.x, acc[i].x);
            acc[i].y = fmaf(a, w.y, acc[i].y);
            acc[i].z = fmaf(a, w.z, acc[i].z);
            acc[i].w = fmaf(a, w.w, acc[i].w);
        }
    }
    float* o = out + ((size_t)(b * KSEL + r)) * DMODEL + n0 + c0;
#pragma unroll
    for (int i = 0; i < 4; i++) *(float4*)&o[i * 4] = acc[i];
}

// ---------------------------------------------------------------------------
extern "C" void kernel_launch(void* const* d_in, const int* in_sizes, int n_in,
                              void* d_out, int out_size)
{
    const float* x      = (const float*)d_in[0];
    const float* W1     = (const float*)d_in[1];
    const float* b1     = (const float*)d_in[2];
    const float* w_sal  = (const float*)d_in[5];
    const float* b_sal  = (const float*)d_in[6];
    const float* mu     = (const float*)d_in[7];
    const float* sigma  = (const float*)d_in[8];
    const float* W_lift = (const float*)d_in[9];
    const float* b_lift = (const float*)d_in[10];
    const float* W_proj = (const float*)d_in[11];
    const float* b_proj = (const float*)d_in[12];
    float* out = (float*)d_out;

    static cudaStream_t s2 = []() {
        cudaStream_t s; cudaStreamCreateWithFlags(&s, cudaStreamNonBlocking); return s;
    }();
    static cudaEvent_t evF = []() {
        cudaEvent_t e; cudaEventCreateWithFlags(&e, cudaEventDisableTiming); return e;
    }();
    static cudaEvent_t evJ = []() {
        cudaEvent_t e; cudaEventCreateWithFlags(&e, cudaEventDisableTiming); return e;
    }();

    cudaEventRecord(evF, 0);
    cudaStreamWaitEvent(s2, evF, 0);
    k_xmean_part<<<dim3(BB, 16), 256, 0, s2>>>(x);
    k_xmean_fin<<<BB, 256, 0, s2>>>();
    cudaEventRecord(evJ, s2);

    k_convert_w<<<dim3(64, 16), 128>>>(W1);
    k_gemm_part<<<dim3(4, 1024), 256>>>(x, b1, w_sal);
    k_selector<<<BB, 1024>>>(b_sal, out);

    cudaStreamWaitEvent(0, evJ, 0);
    k_lift<<<dim3(BB, KSEL), 256>>>(x, mu, sigma, W_lift, b_lift);
    k_proj<<<dim3(BB, 8), 256>>>(W_proj, b_proj, out);
}

// round 14
// speedup vs baseline: 1.1782x; 1.0406x over previous
#include <cuda_runtime.h>
#include <cuda_bf16.h>
#include <cstdint>
#include <math.h>

#define BB 32
#define TT 4096
#define DIN 256
#define HID 512
#define AD 259
#define KLIFT 64
#define DMODEL 1024
#define KSEL 32
#define PGD_STEPS 60

// ---------------- scratch (device globals; no allocation allowed) ----------
__device__ float g_sal[BB * TT];
__device__ float g_spart[4][BB * TT];        // per-N-tile partial saliency dot
__device__ float g_xpart[16 * BB * DIN];
__device__ float g_xmean[BB * DIN];
__device__ float g_msal[BB];
__device__ int   g_topidx[BB * KSEL];
__device__ float g_cloud[BB * KSEL * KLIFT];
// W1 pre-fragmented for mma.sync B operand: [n_tile 64][k_chunk 16][lane 32]
__device__ uint2 g_BfH[64 * 16 * 32];
__device__ uint2 g_BfL[64 * 16 * 32];

__device__ __forceinline__ uint32_t pack_bf2(__nv_bfloat16 a, __nv_bfloat16 b) {
    return (uint32_t)__bfloat16_as_ushort(a) | ((uint32_t)__bfloat16_as_ushort(b) << 16);
}

// mma.sync m16n8k16 row.col f32.bf16.bf16.f32 (portable PTX, HMMA pipe)
__device__ __forceinline__ void mma_bf16(float* d, const uint32_t* a, const uint32_t* b) {
    asm volatile(
        "mma.sync.aligned.m16n8k16.row.col.f32.bf16.bf16.f32 "
        "{%0,%1,%2,%3}, {%4,%5,%6,%7}, {%8,%9}, {%0,%1,%2,%3};"
        : "+f"(d[0]), "+f"(d[1]), "+f"(d[2]), "+f"(d[3])
        : "r"(a[0]), "r"(a[1]), "r"(a[2]), "r"(a[3]), "r"(b[0]), "r"(b[1]));
}

// ldmatrix x4: loads 4 8x8 b16 matrices; lane supplies one 16B row address.
__device__ __forceinline__ void ldsm_x4(uint32_t* r, uint32_t saddr) {
    asm volatile(
        "ldmatrix.sync.aligned.m8n8.x4.shared.b16 {%0,%1,%2,%3}, [%4];"
        : "=r"(r[0]), "=r"(r[1]), "=r"(r[2]), "=r"(r[3]) : "r"(saddr));
}

__device__ __forceinline__ uint32_t smem_u32(const void* p) {
    return (uint32_t)__cvta_generic_to_shared(p);
}
// 16B-unit swizzle: distinct banks for all STS/LDSM phases
__device__ __forceinline__ uint32_t su16(uint32_t u) { return u ^ ((u >> 3) & 1u); }

// trunc-split of a float4 into bf16 hi (2 PRMT) + lo (2 FADD-pairs + cvt.bf16x2)
__device__ __forceinline__ void split4(float4 v, uint2* hi, uint2* lo) {
    uint32_t b0 = __float_as_uint(v.x), b1 = __float_as_uint(v.y);
    uint32_t b2 = __float_as_uint(v.z), b3 = __float_as_uint(v.w);
    hi->x = __byte_perm(b0, b1, 0x7632);
    hi->y = __byte_perm(b2, b3, 0x7632);
    float l0 = v.x - __uint_as_float(b0 & 0xFFFF0000u);
    float l1 = v.y - __uint_as_float(b1 & 0xFFFF0000u);
    float l2 = v.z - __uint_as_float(b2 & 0xFFFF0000u);
    float l3 = v.w - __uint_as_float(b3 & 0xFFFF0000u);
    __nv_bfloat162 p0 = __float22bfloat162_rn(make_float2(l0, l1));
    __nv_bfloat162 p1 = __float22bfloat162_rn(make_float2(l2, l3));
    lo->x = *(uint32_t*)&p0;
    lo->y = *(uint32_t*)&p1;
}

__device__ __forceinline__ float clip01(float v) {
    return fminf(fmaxf(v, 0.f), 1.f);
}

// ---------------------------------------------------------------------------
// Kernel 0: W1 -> bf16 hi/lo (RNE) in mma B-fragment order (coalesced stage).
// ---------------------------------------------------------------------------
__global__ __launch_bounds__(128) void k_convert_w(const float* __restrict__ W1)
{
    __shared__ float sm[16][8];
    const int nt = blockIdx.x, kc = blockIdx.y, tid = threadIdx.x;
    sm[tid >> 3][tid & 7] =
        W1[(size_t)(kc * 16 + (tid >> 3)) * HID + nt * 8 + (tid & 7)];
    __syncthreads();
    if (tid < 32) {
        const int n = tid >> 2, kq = (tid & 3) * 2;
        float v00 = sm[kq][n],     v01 = sm[kq + 1][n];
        float v10 = sm[kq + 8][n], v11 = sm[kq + 9][n];
        __nv_bfloat16 h00 = __float2bfloat16(v00), h01 = __float2bfloat16(v01);
        __nv_bfloat16 h10 = __float2bfloat16(v10), h11 = __float2bfloat16(v11);
        __nv_bfloat16 l00 = __float2bfloat16(v00 - __bfloat162float(h00));
        __nv_bfloat16 l01 = __float2bfloat16(v01 - __bfloat162float(h01));
        __nv_bfloat16 l10 = __float2bfloat16(v10 - __bfloat162float(h10));
        __nv_bfloat16 l11 = __float2bfloat16(v11 - __bfloat162float(h11));
        const int o = (nt * 16 + kc) * 32 + tid;
        g_BfH[o] = make_uint2(pack_bf2(h00, h01), pack_bf2(h10, h11));
        g_BfL[o] = make_uint2(pack_bf2(l00, l01), pack_bf2(l10, l11));
    }
}

// ---------------------------------------------------------------------------
// Kernel 1: bf16-split GEMM via mma.sync (AhBh + AlBh + AhBl)  [R10 layout]
// ---------------------------------------------------------------------------
__global__ __launch_bounds__(256, 2) void k_gemm_part(
    const float* __restrict__ x, const float* __restrict__ b1,
    const float* __restrict__ w_sal)
{
    __shared__ __align__(16) unsigned char sA[2][2][4096];
    __shared__ float part[4][128];
    __shared__ float sB1[128], sWs[128];

    const int tid = threadIdx.x;
    const int n0 = blockIdx.x * 128;
    const int m0 = blockIdx.y * 128;
    const int lane = tid & 31, wid = tid >> 5;
    const int wm = (wid >> 2) * 64, wn = (wid & 3) * 32;
    const int g = lane >> 2, t = lane & 3;
    const int ntbase = (n0 >> 3) + ((wid & 3) * 4);

    if (tid < 128) { sB1[tid] = b1[n0 + tid]; sWs[tid] = w_sal[n0 + tid]; }

    const int arow = tid >> 2, aseg = tid & 3;
    const uint32_t offA = su16((uint32_t)(arow * 2 + (aseg >> 1))) * 16
                        + (uint32_t)(aseg & 1) * 8;
    const uint32_t offB = su16((uint32_t)((arow + 64) * 2 + (aseg >> 1))) * 16
                        + (uint32_t)(aseg & 1) * 8;

    uint32_t frOff[4];
    {
        const int r8 = lane & 7, hr = (lane >> 3) & 1, hc = (lane >> 4) & 1;
#pragma unroll
        for (int mi = 0; mi < 4; mi++) {
            uint32_t row = (uint32_t)(wm + mi * 16 + hr * 8 + r8);
            frOff[mi] = su16(row * 2 + (uint32_t)hc) * 16;
        }
    }
    const uint32_t baseH[2] = {smem_u32(&sA[0][0][0]), smem_u32(&sA[1][0][0])};
    const uint32_t baseL[2] = {smem_u32(&sA[0][1][0]), smem_u32(&sA[1][1][0])};

    float acc[4][4][4];
#pragma unroll
    for (int mi = 0; mi < 4; mi++)
#pragma unroll
        for (int ni = 0; ni < 4; ni++)
#pragma unroll
            for (int q = 0; q < 4; q++) acc[mi][ni][q] = 0.f;

    float4 pa0, pa1;
    pa0 = *(const float4*)&x[(size_t)(m0 + arow) * DIN + aseg * 4];
    pa1 = *(const float4*)&x[(size_t)(m0 + arow + 64) * DIN + aseg * 4];

    for (int s = 0; s < 16; s++) {
        const int buf = s & 1;
        uint2 fbh[4], fbl[4];
#pragma unroll
        for (int ni = 0; ni < 4; ni++) {
            const int o = ((ntbase + ni) * 16 + s) * 32 + lane;
            fbh[ni] = g_BfH[o];
            fbl[ni] = g_BfL[o];
        }
        {
            uint2 h0, l0, h1, l1;
            split4(pa0, &h0, &l0);
            split4(pa1, &h1, &l1);
            *(uint2*)&sA[buf][0][offA] = h0;
            *(uint2*)&sA[buf][1][offA] = l0;
            *(uint2*)&sA[buf][0][offB] = h1;
            *(uint2*)&sA[buf][1][offB] = l1;
        }
        __syncthreads();
        if (s < 15) {
            pa0 = *(const float4*)&x[(size_t)(m0 + arow) * DIN + (s + 1) * 16 + aseg * 4];
            pa1 = *(const float4*)&x[(size_t)(m0 + arow + 64) * DIN + (s + 1) * 16 + aseg * 4];
        }

        uint32_t bh[4][2], bl[4][2];
#pragma unroll
        for (int ni = 0; ni < 4; ni++) {
            bh[ni][0] = fbh[ni].x; bh[ni][1] = fbh[ni].y;
            bl[ni][0] = fbl[ni].x; bl[ni][1] = fbl[ni].y;
        }
        uint32_t ah[4][4], al[4][4];
#pragma unroll
        for (int mi = 0; mi < 4; mi++) ldsm_x4(ah[mi], baseH[buf] + frOff[mi]);
#pragma unroll
        for (int mi = 0; mi < 4; mi++)
#pragma unroll
            for (int ni = 0; ni < 4; ni++)
                mma_bf16(acc[mi][ni], ah[mi], bh[ni]);
#pragma unroll
        for (int mi = 0; mi < 4; mi++)
#pragma unroll
            for (int ni = 0; ni < 4; ni++)
                mma_bf16(acc[mi][ni], ah[mi], bl[ni]);
#pragma unroll
        for (int mi = 0; mi < 4; mi++) ldsm_x4(al[mi], baseL[buf] + frOff[mi]);
#pragma unroll
        for (int mi = 0; mi < 4; mi++)
#pragma unroll
            for (int ni = 0; ni < 4; ni++)
                mma_bf16(acc[mi][ni], al[mi], bh[ni]);
    }

    float rsum[4][2];
#pragma unroll
    for (int mi = 0; mi < 4; mi++) { rsum[mi][0] = 0.f; rsum[mi][1] = 0.f; }
#pragma unroll
    for (int mi = 0; mi < 4; mi++)
#pragma unroll
        for (int ni = 0; ni < 4; ni++) {
            int c0 = wn + ni * 8 + t * 2;
            float w0 = sWs[c0], w1 = sWs[c0 + 1];
            float bb0 = sB1[c0], bb1 = sB1[c0 + 1];
            rsum[mi][0] += tanhf(acc[mi][ni][0] + bb0) * w0
                         + tanhf(acc[mi][ni][1] + bb1) * w1;
            rsum[mi][1] += tanhf(acc[mi][ni][2] + bb0) * w0
                         + tanhf(acc[mi][ni][3] + bb1) * w1;
        }
#pragma unroll
    for (int mi = 0; mi < 4; mi++)
#pragma unroll
        for (int sel = 0; sel < 2; sel++) {
            float v = rsum[mi][sel];
            v += __shfl_xor_sync(0xffffffffu, v, 1);
            v += __shfl_xor_sync(0xffffffffu, v, 2);
            if (t == 0) part[wid & 3][wm + mi * 16 + sel * 8 + g] = v;
        }
    __syncthreads();
    if (tid < 128) {
        float v = ((part[0][tid] + part[1][tid]) + part[2][tid]) + part[3][tid];
        g_spart[blockIdx.x][m0 + tid] = v;
    }
}

// ---------------------------------------------------------------------------
// Kernel 2a/2b: mean of x over T per batch (deterministic two-stage)
// ---------------------------------------------------------------------------
__global__ void k_xmean_part(const float* __restrict__ x)
{
    int b = blockIdx.x, ch = blockIdx.y, d = threadIdx.x;
    const float* base = x + ((size_t)b * TT + ch * 256) * DIN + d;
    float acc = 0.f;
    for (int t = 0; t < 256; t++) acc += base[(size_t)t * DIN];
    g_xpart[(ch * BB + b) * DIN + d] = acc;
}
__global__ void k_xmean_fin()
{
    int b = blockIdx.x, d = threadIdx.x;
    float acc = 0.f;
    for (int ch = 0; ch < 16; ch++) acc += g_xpart[(ch * BB + b) * DIN + d];
    g_xmean[b * DIN + d] = acc * (1.0f / TT);
}

// ---------------------------------------------------------------------------
// Kernel 3: fused sal-finalize + PGD selector.
// 512 threads x 8 elems. Newton cap 5 with exact-equality break (uniform:
// butterfly allreduce is bitwise-identical on all lanes). z-publication:
// buffers hold pre-projection z; neighbors apply clip(z - tau_prev).
// ---------------------------------------------------------------------------
__global__ __launch_bounds__(512) void k_selector(
    const float* __restrict__ b_sal, float* __restrict__ d_out)
{
    __shared__ float zsA[TT];
    __shared__ float zsB[TT];
    __shared__ float redS[2][16], redC[2][16];
    __shared__ float redT[2][16];
    __shared__ int   redi[2][16];

    const int b = blockIdx.x;
    const int tid = threadIdx.x;
    const int lane = tid & 31, wid = tid >> 5;   // 16 warps
    const int i0 = tid * 8;

    const float bs = b_sal[0];
    float s[8];
#pragma unroll
    for (int h = 0; h < 2; h++) {
        float4 p0 = *(const float4*)&g_spart[0][b * TT + i0 + h * 4];
        float4 p1 = *(const float4*)&g_spart[1][b * TT + i0 + h * 4];
        float4 p2 = *(const float4*)&g_spart[2][b * TT + i0 + h * 4];
        float4 p3 = *(const float4*)&g_spart[3][b * TT + i0 + h * 4];
        float zz[4];
        zz[0] = ((p0.x + p1.x) + p2.x) + p3.x + bs;
        zz[1] = ((p0.y + p1.y) + p2.y) + p3.y + bs;
        zz[2] = ((p0.z + p1.z) + p2.z) + p3.z + bs;
        zz[3] = ((p0.w + p1.w) + p2.w) + p3.w + bs;
        float4 so;
#pragma unroll
        for (int q = 0; q < 4; q++) {
            float v = fmaxf(zz[q], 0.f) + log1pf(expf(-fabsf(zz[q])));
            s[h * 4 + q] = v;
            ((float*)&so)[q] = v;
        }
        *(float4*)&g_sal[b * TT + i0 + h * 4] = so;
    }

    float y[8];
#pragma unroll
    for (int q = 0; q < 8; q++) y[q] = 0.0078125f;
    *(float4*)&zsA[i0] = make_float4(y[0], y[1], y[2], y[3]);
    *(float4*)&zsA[i0 + 4] = make_float4(y[4], y[5], y[6], y[7]);
    __syncthreads();

    float tau_prev = 0.f;
    for (int step = 0; step < PGD_STEPS; step++) {
        const float* rd = (step & 1) ? zsB : zsA;
        float*       wr = (step & 1) ? zsA : zsB;

        float yv[12];
        yv[0] = (i0 > 0) ? clip01(rd[i0 - 2] - tau_prev) : 0.f;
        yv[1] = (i0 > 0) ? clip01(rd[i0 - 1] - tau_prev) : 0.f;
#pragma unroll
        for (int q = 0; q < 8; q++) yv[2 + q] = y[q];
        yv[10] = (i0 + 8 < TT) ? clip01(rd[i0 + 8] - tau_prev) : 0.f;
        yv[11] = (i0 + 8 < TT) ? clip01(rd[i0 + 9] - tau_prev) : 0.f;

        float z[8];
#pragma unroll
        for (int q = 0; q < 8; q++) {
            // reference order: (((+1) + (-1)) + (+2)) + (-2)
            float nb = ((yv[q + 3] + yv[q + 1]) + yv[q + 4]) + yv[q];
            float g = (s[q] - y[q]) - 0.5f * nb;
            z[q] = clip01(y[q] + 0.1f * g);
        }
        *(float4*)&wr[i0] = make_float4(z[0], z[1], z[2], z[3]);
        *(float4*)&wr[i0 + 4] = make_float4(z[4], z[5], z[6], z[7]);

        float tau = tau_prev;
        for (int it = 0; it < 5; it++) {
            const int p = it & 1;
            float ls = 0.f, lc = 0.f;
#pragma unroll
            for (int q = 0; q < 8; q++)
                if (z[q] > tau) { ls += z[q]; lc += 1.f; }
#pragma unroll
            for (int o = 16; o; o >>= 1) {
                ls += __shfl_xor_sync(0xffffffffu, ls, o);
                lc += __shfl_xor_sync(0xffffffffu, lc, o);
            }
            if (lane == 0) { redS[p][wid] = ls; redC[p][wid] = lc; }
            __syncthreads();
            float S = redS[p][lane & 15], C = redC[p][lane & 15];
#pragma unroll
            for (int o = 8; o; o >>= 1) {
                S += __shfl_xor_sync(0xffffffffu, S, o);
                C += __shfl_xor_sync(0xffffffffu, C, o);
            }
            float tnew = (C >= 1.f) ? fmaxf((S - 32.f) / C, 0.f) : 0.f;
            if (tnew == tau) break;     // uniform fixpoint
            tau = tnew;
        }
        tau_prev = tau;
#pragma unroll
        for (int q = 0; q < 8; q++)
            y[q] = clip01(z[q] - tau);
    }
    __syncthreads();

    float* outY = d_out + (size_t)BB * KSEL * DMODEL + (size_t)b * TT;
    *(float4*)&outY[i0] = make_float4(y[0], y[1], y[2], y[3]);
    *(float4*)&outY[i0 + 4] = make_float4(y[4], y[5], y[6], y[7]);

    {
        float ms = s[0];
#pragma unroll
        for (int q = 1; q < 8; q++) ms += s[q];
#pragma unroll
        for (int o = 16; o; o >>= 1) ms += __shfl_xor_sync(0xffffffffu, ms, o);
        if (lane == 0) redS[0][wid] = ms;
        __syncthreads();
        if (tid < 32) {
            float v = redS[0][lane & 15];
#pragma unroll
            for (int o = 8; o; o >>= 1) v += __shfl_xor_sync(0xffffffffu, v, o);
            if (lane == 0) g_msal[b] = v * (1.0f / TT);
        }
        __syncthreads();
    }

    // ---- top-32 iterative argmax (value desc, index asc on ties) ----
    float mval[8];
#pragma unroll
    for (int q = 0; q < 8; q++) mval[q] = y[q];
    for (int sel = 0; sel < KSEL; sel++) {
        const int p = sel & 1;
        float bv = -1.f; int bi = TT;
#pragma unroll
        for (int q = 0; q < 8; q++)
            if (mval[q] > bv) { bv = mval[q]; bi = i0 + q; }
#pragma unroll
        for (int o = 16; o; o >>= 1) {
            float ov = __shfl_xor_sync(0xffffffffu, bv, o);
            int   oi = __shfl_xor_sync(0xffffffffu, bi, o);
            if (ov > bv || (ov == bv && oi < bi)) { bv = ov; bi = oi; }
        }
        if (lane == 0) { redT[p][wid] = bv; redi[p][wid] = bi; }
        __syncthreads();
        bv = redT[p][lane & 15]; bi = redi[p][lane & 15];
#pragma unroll
        for (int o = 8; o; o >>= 1) {
            float ov = __shfl_xor_sync(0xffffffffu, bv, o);
            int   oi = __shfl_xor_sync(0xffffffffu, bi, o);
            if (ov > bv || (ov == bv && oi < bi)) { bv = ov; bi = oi; }
        }
        if (tid == 0) g_topidx[b * KSEL + sel] = bi;
        if ((bi >> 3) == tid) mval[bi & 7] = -1.f;
    }
}

// ---------------------------------------------------------------------------
// Kernel 4a: gather + anchor vector + lift (259->64) -> g_cloud
// ---------------------------------------------------------------------------
__global__ __launch_bounds__(256) void k_lift(
    const float* __restrict__ x, const float* __restrict__ mu,
    const float* __restrict__ sigma, const float* __restrict__ W_lift,
    const float* __restrict__ b_lift)
{
    __shared__ float u[AD];
    __shared__ float partl[4][KLIFT];
    const int b = blockIdx.x, j = blockIdx.y;
    const int tid = threadIdx.x;
    const int idx = g_topidx[b * KSEL + j];

    {
        float v = x[((size_t)b * TT + idx) * DIN + tid] - g_xmean[b * DIN + tid];
        u[tid] = (v - mu[tid]) / sigma[tid];
    }
    if (tid == 0) {
        float sali = g_sal[b * TT + idx];
        float ms = g_msal[b];
        u[256] = ((sali - ms) - mu[256]) / sigma[256];
        float tn = (float)idx * (1.0f / 4096.0f);
        u[257] = ((tn - 0.4998779296875f) - mu[257]) / sigma[257];
        float ds = (idx == 0) ? 0.f : (sali - g_sal[b * TT + idx - 1]);
        float mds = (g_sal[b * TT + TT - 1] - g_sal[b * TT]) * (1.0f / 4096.0f);
        u[258] = ((ds - mds) - mu[258]) / sigma[258];
    }
    __syncthreads();

    {
        const int kk = tid & 63, pp = tid >> 6;
        const int d0 = pp * 65;
        const int d1 = (pp == 3) ? AD : d0 + 65;
        float acc = 0.f;
        for (int d = d0; d < d1; d++)
            acc = fmaf(u[d], W_lift[d * KLIFT + kk], acc);
        partl[pp][kk] = acc;
    }
    __syncthreads();
    if (tid < KLIFT) {
        float v = b_lift[tid]
                + (((partl[0][tid] + partl[1][tid]) + partl[2][tid]) + partl[3][tid]);
        g_cloud[(b * KSEL + j) * KLIFT + tid] = v;
    }
}

// ---------------------------------------------------------------------------
// Kernel 4b: tokens = cloud[b,32,64] @ W_proj[64,1024] + b_proj
// ---------------------------------------------------------------------------
__global__ __launch_bounds__(256) void k_proj(
    const float* __restrict__ W_proj, const float* __restrict__ b_proj,
    float* __restrict__ out)
{
    __shared__ float sW[KLIFT][128];
    __shared__ float sC[KSEL][KLIFT];
    const int b = blockIdx.x, n0 = blockIdx.y * 128;
    const int tid = threadIdx.x;

#pragma unroll
    for (int it = 0; it < 8; it++) {
        int i = tid + it * 256;
        int k = i >> 5, c4 = i & 31;
        *(float4*)&sW[k][c4 * 4] =
            *(const float4*)&W_proj[(size_t)k * DMODEL + n0 + c4 * 4];
    }
#pragma unroll
    for (int it = 0; it < 2; it++) {
        int i = tid + it * 256;
        int r = i >> 4, c4 = i & 15;
        *(float4*)&sC[r][c4 * 4] =
            *(const float4*)&g_cloud[(b * KSEL + r) * KLIFT + c4 * 4];
    }
    __syncthreads();

    const int r = tid >> 3;
    const int c0 = (tid & 7) * 16;
    float4 acc[4];
#pragma unroll
    for (int i = 0; i < 4; i++)
        acc[i] = *(const float4*)&b_proj[n0 + c0 + i * 4];
#pragma unroll
    for (int k = 0; k < KLIFT; k++) {
        float a = sC[r][k];
#pragma unroll
        for (int i = 0; i < 4; i++) {
            float4 w = *(const float4*)&sW[k][c0 + i * 4];
            acc[i].x = fmaf(a, w.x, acc[i].x);
            acc[i].y = fmaf(a, w.y, acc[i].y);
            acc[i].z = fmaf(a, w.z, acc[i].z);
            acc[i].w = fmaf(a, w.w, acc[i].w);
        }
    }
    float* o = out + ((size_t)(b * KSEL + r)) * DMODEL + n0 + c0;
#pragma unroll
    for (int i = 0; i < 4; i++) *(float4*)&o[i * 4] = acc[i];
}

// ---------------------------------------------------------------------------
extern "C" void kernel_launch(void* const* d_in, const int* in_sizes, int n_in,
                              void* d_out, int out_size)
{
    const float* x      = (const float*)d_in[0];
    const float* W1     = (const float*)d_in[1];
    const float* b1     = (const float*)d_in[2];
    const float* w_sal  = (const float*)d_in[5];
    const float* b_sal  = (const float*)d_in[6];
    const float* mu     = (const float*)d_in[7];
    const float* sigma  = (const float*)d_in[8];
    const float* W_lift = (const float*)d_in[9];
    const float* b_lift = (const float*)d_in[10];
    const float* W_proj = (const float*)d_in[11];
    const float* b_proj = (const float*)d_in[12];
    float* out = (float*)d_out;

    static cudaStream_t s2 = []() {
        cudaStream_t s; cudaStreamCreateWithFlags(&s, cudaStreamNonBlocking); return s;
    }();
    static cudaEvent_t evF = []() {
        cudaEvent_t e; cudaEventCreateWithFlags(&e, cudaEventDisableTiming); return e;
    }();
    static cudaEvent_t evJ = []() {
        cudaEvent_t e; cudaEventCreateWithFlags(&e, cudaEventDisableTiming); return e;
    }();

    cudaEventRecord(evF, 0);
    cudaStreamWaitEvent(s2, evF, 0);
    k_xmean_part<<<dim3(BB, 16), 256, 0, s2>>>(x);
    k_xmean_fin<<<BB, 256, 0, s2>>>();
    cudaEventRecord(evJ, s2);

    k_convert_w<<<dim3(64, 16), 128>>>(W1);
    k_gemm_part<<<dim3(4, 1024), 256>>>(x, b1, w_sal);
    k_selector<<<BB, 512>>>(b_sal, out);

    cudaStreamWaitEvent(0, evJ, 0);
    k_lift<<<dim3(BB, KSEL), 256>>>(x, mu, sigma, W_lift, b_lift);
    k_proj<<<dim3(BB, 8), 256>>>(W_proj, b_proj, out);
}

// round 15
// speedup vs baseline: 1.2741x; 1.0814x over previous
#include <cuda_runtime.h>
#include <cuda_bf16.h>
#include <cstdint>
#include <math.h>

#define BB 32
#define TT 4096
#define DIN 256
#define HID 512
#define AD 259
#define KLIFT 64
#define DMODEL 1024
#define KSEL 32
#define PGD_STEPS 60

// ---------------- scratch (device globals; no allocation allowed) ----------
__device__ float g_sal[BB * TT];
__device__ float g_spart[4][BB * TT];        // per-N-tile partial saliency dot
__device__ float g_xpart[16 * BB * DIN];
__device__ float g_xmean[BB * DIN];
__device__ float g_msal[BB];
__device__ int   g_topidx[BB * KSEL];
__device__ float g_cloud[BB * KSEL * KLIFT];
// W1 pre-fragmented for mma.sync B operand: [n_tile 64][k_chunk 16][lane 32]
__device__ uint2 g_BfH[64 * 16 * 32];
__device__ uint2 g_BfL[64 * 16 * 32];

__device__ __forceinline__ uint32_t pack_bf2(__nv_bfloat16 a, __nv_bfloat16 b) {
    return (uint32_t)__bfloat16_as_ushort(a) | ((uint32_t)__bfloat16_as_ushort(b) << 16);
}

// mma.sync m16n8k16 row.col f32.bf16.bf16.f32 (portable PTX, HMMA pipe)
__device__ __forceinline__ void mma_bf16(float* d, const uint32_t* a, const uint32_t* b) {
    asm volatile(
        "mma.sync.aligned.m16n8k16.row.col.f32.bf16.bf16.f32 "
        "{%0,%1,%2,%3}, {%4,%5,%6,%7}, {%8,%9}, {%0,%1,%2,%3};"
        : "+f"(d[0]), "+f"(d[1]), "+f"(d[2]), "+f"(d[3])
        : "r"(a[0]), "r"(a[1]), "r"(a[2]), "r"(a[3]), "r"(b[0]), "r"(b[1]));
}

// ldmatrix x4: loads 4 8x8 b16 matrices; lane supplies one 16B row address.
__device__ __forceinline__ void ldsm_x4(uint32_t* r, uint32_t saddr) {
    asm volatile(
        "ldmatrix.sync.aligned.m8n8.x4.shared.b16 {%0,%1,%2,%3}, [%4];"
        : "=r"(r[0]), "=r"(r[1]), "=r"(r[2]), "=r"(r[3]) : "r"(saddr));
}

__device__ __forceinline__ uint32_t smem_u32(const void* p) {
    return (uint32_t)__cvta_generic_to_shared(p);
}
// 16B-unit swizzle: distinct banks for all STS/LDSM phases
__device__ __forceinline__ uint32_t su16(uint32_t u) { return u ^ ((u >> 3) & 1u); }

// trunc-split of a float4 into bf16 hi (2 PRMT) + lo (2 FADD-pairs + cvt.bf16x2)
__device__ __forceinline__ void split4(float4 v, uint2* hi, uint2* lo) {
    uint32_t b0 = __float_as_uint(v.x), b1 = __float_as_uint(v.y);
    uint32_t b2 = __float_as_uint(v.z), b3 = __float_as_uint(v.w);
    hi->x = __byte_perm(b0, b1, 0x7632);
    hi->y = __byte_perm(b2, b3, 0x7632);
    float l0 = v.x - __uint_as_float(b0 & 0xFFFF0000u);
    float l1 = v.y - __uint_as_float(b1 & 0xFFFF0000u);
    float l2 = v.z - __uint_as_float(b2 & 0xFFFF0000u);
    float l3 = v.w - __uint_as_float(b3 & 0xFFFF0000u);
    __nv_bfloat162 p0 = __float22bfloat162_rn(make_float2(l0, l1));
    __nv_bfloat162 p1 = __float22bfloat162_rn(make_float2(l2, l3));
    lo->x = *(uint32_t*)&p0;
    lo->y = *(uint32_t*)&p1;
}

__device__ __forceinline__ float clip01(float v) {
    return fminf(fmaxf(v, 0.f), 1.f);
}

// ---------------------------------------------------------------------------
// Kernel 0: W1 -> bf16 hi/lo (RNE) in mma B-fragment order (coalesced stage).
// ---------------------------------------------------------------------------
__global__ __launch_bounds__(128) void k_convert_w(const float* __restrict__ W1)
{
    __shared__ float sm[16][8];
    const int nt = blockIdx.x, kc = blockIdx.y, tid = threadIdx.x;
    sm[tid >> 3][tid & 7] =
        W1[(size_t)(kc * 16 + (tid >> 3)) * HID + nt * 8 + (tid & 7)];
    __syncthreads();
    if (tid < 32) {
        const int n = tid >> 2, kq = (tid & 3) * 2;
        float v00 = sm[kq][n],     v01 = sm[kq + 1][n];
        float v10 = sm[kq + 8][n], v11 = sm[kq + 9][n];
        __nv_bfloat16 h00 = __float2bfloat16(v00), h01 = __float2bfloat16(v01);
        __nv_bfloat16 h10 = __float2bfloat16(v10), h11 = __float2bfloat16(v11);
        __nv_bfloat16 l00 = __float2bfloat16(v00 - __bfloat162float(h00));
        __nv_bfloat16 l01 = __float2bfloat16(v01 - __bfloat162float(h01));
        __nv_bfloat16 l10 = __float2bfloat16(v10 - __bfloat162float(h10));
        __nv_bfloat16 l11 = __float2bfloat16(v11 - __bfloat162float(h11));
        const int o = (nt * 16 + kc) * 32 + tid;
        g_BfH[o] = make_uint2(pack_bf2(h00, h01), pack_bf2(h10, h11));
        g_BfL[o] = make_uint2(pack_bf2(l00, l01), pack_bf2(l10, l11));
    }
}

// ---------------------------------------------------------------------------
// Kernel 1: bf16-split GEMM via mma.sync (AhBh + AlBh + AhBl)  [R10 layout]
// ---------------------------------------------------------------------------
__global__ __launch_bounds__(256, 2) void k_gemm_part(
    const float* __restrict__ x, const float* __restrict__ b1,
    const float* __restrict__ w_sal)
{
    __shared__ __align__(16) unsigned char sA[2][2][4096];
    __shared__ float part[4][128];
    __shared__ float sB1[128], sWs[128];

    const int tid = threadIdx.x;
    const int n0 = blockIdx.x * 128;
    const int m0 = blockIdx.y * 128;
    const int lane = tid & 31, wid = tid >> 5;
    const int wm = (wid >> 2) * 64, wn = (wid & 3) * 32;
    const int g = lane >> 2, t = lane & 3;
    const int ntbase = (n0 >> 3) + ((wid & 3) * 4);

    if (tid < 128) { sB1[tid] = b1[n0 + tid]; sWs[tid] = w_sal[n0 + tid]; }

    const int arow = tid >> 2, aseg = tid & 3;
    const uint32_t offA = su16((uint32_t)(arow * 2 + (aseg >> 1))) * 16
                        + (uint32_t)(aseg & 1) * 8;
    const uint32_t offB = su16((uint32_t)((arow + 64) * 2 + (aseg >> 1))) * 16
                        + (uint32_t)(aseg & 1) * 8;

    uint32_t frOff[4];
    {
        const int r8 = lane & 7, hr = (lane >> 3) & 1, hc = (lane >> 4) & 1;
#pragma unroll
        for (int mi = 0; mi < 4; mi++) {
            uint32_t row = (uint32_t)(wm + mi * 16 + hr * 8 + r8);
            frOff[mi] = su16(row * 2 + (uint32_t)hc) * 16;
        }
    }
    const uint32_t baseH[2] = {smem_u32(&sA[0][0][0]), smem_u32(&sA[1][0][0])};
    const uint32_t baseL[2] = {smem_u32(&sA[0][1][0]), smem_u32(&sA[1][1][0])};

    float acc[4][4][4];
#pragma unroll
    for (int mi = 0; mi < 4; mi++)
#pragma unroll
        for (int ni = 0; ni < 4; ni++)
#pragma unroll
            for (int q = 0; q < 4; q++) acc[mi][ni][q] = 0.f;

    float4 pa0, pa1;
    pa0 = *(const float4*)&x[(size_t)(m0 + arow) * DIN + aseg * 4];
    pa1 = *(const float4*)&x[(size_t)(m0 + arow + 64) * DIN + aseg * 4];

    for (int s = 0; s < 16; s++) {
        const int buf = s & 1;
        uint2 fbh[4], fbl[4];
#pragma unroll
        for (int ni = 0; ni < 4; ni++) {
            const int o = ((ntbase + ni) * 16 + s) * 32 + lane;
            fbh[ni] = g_BfH[o];
            fbl[ni] = g_BfL[o];
        }
        {
            uint2 h0, l0, h1, l1;
            split4(pa0, &h0, &l0);
            split4(pa1, &h1, &l1);
            *(uint2*)&sA[buf][0][offA] = h0;
            *(uint2*)&sA[buf][1][offA] = l0;
            *(uint2*)&sA[buf][0][offB] = h1;
            *(uint2*)&sA[buf][1][offB] = l1;
        }
        __syncthreads();
        if (s < 15) {
            pa0 = *(const float4*)&x[(size_t)(m0 + arow) * DIN + (s + 1) * 16 + aseg * 4];
            pa1 = *(const float4*)&x[(size_t)(m0 + arow + 64) * DIN + (s + 1) * 16 + aseg * 4];
        }

        uint32_t bh[4][2], bl[4][2];
#pragma unroll
        for (int ni = 0; ni < 4; ni++) {
            bh[ni][0] = fbh[ni].x; bh[ni][1] = fbh[ni].y;
            bl[ni][0] = fbl[ni].x; bl[ni][1] = fbl[ni].y;
        }
        uint32_t ah[4][4], al[4][4];
#pragma unroll
        for (int mi = 0; mi < 4; mi++) ldsm_x4(ah[mi], baseH[buf] + frOff[mi]);
#pragma unroll
        for (int mi = 0; mi < 4; mi++)
#pragma unroll
            for (int ni = 0; ni < 4; ni++)
                mma_bf16(acc[mi][ni], ah[mi], bh[ni]);
#pragma unroll
        for (int mi = 0; mi < 4; mi++)
#pragma unroll
            for (int ni = 0; ni < 4; ni++)
                mma_bf16(acc[mi][ni], ah[mi], bl[ni]);
#pragma unroll
        for (int mi = 0; mi < 4; mi++) ldsm_x4(al[mi], baseL[buf] + frOff[mi]);
#pragma unroll
        for (int mi = 0; mi < 4; mi++)
#pragma unroll
            for (int ni = 0; ni < 4; ni++)
                mma_bf16(acc[mi][ni], al[mi], bh[ni]);
    }

    float rsum[4][2];
#pragma unroll
    for (int mi = 0; mi < 4; mi++) { rsum[mi][0] = 0.f; rsum[mi][1] = 0.f; }
#pragma unroll
    for (int mi = 0; mi < 4; mi++)
#pragma unroll
        for (int ni = 0; ni < 4; ni++) {
            int c0 = wn + ni * 8 + t * 2;
            float w0 = sWs[c0], w1 = sWs[c0 + 1];
            float bb0 = sB1[c0], bb1 = sB1[c0 + 1];
            rsum[mi][0] += tanhf(acc[mi][ni][0] + bb0) * w0
                         + tanhf(acc[mi][ni][1] + bb1) * w1;
            rsum[mi][1] += tanhf(acc[mi][ni][2] + bb0) * w0
                         + tanhf(acc[mi][ni][3] + bb1) * w1;
        }
#pragma unroll
    for (int mi = 0; mi < 4; mi++)
#pragma unroll
        for (int sel = 0; sel < 2; sel++) {
            float v = rsum[mi][sel];
            v += __shfl_xor_sync(0xffffffffu, v, 1);
            v += __shfl_xor_sync(0xffffffffu, v, 2);
            if (t == 0) part[wid & 3][wm + mi * 16 + sel * 8 + g] = v;
        }
    __syncthreads();
    if (tid < 128) {
        float v = ((part[0][tid] + part[1][tid]) + part[2][tid]) + part[3][tid];
        g_spart[blockIdx.x][m0 + tid] = v;
    }
}

// ---------------------------------------------------------------------------
// Kernel 2a/2b: mean of x over T per batch (deterministic two-stage)
// ---------------------------------------------------------------------------
__global__ void k_xmean_part(const float* __restrict__ x)
{
    int b = blockIdx.x, ch = blockIdx.y, d = threadIdx.x;
    const float* base = x + ((size_t)b * TT + ch * 256) * DIN + d;
    float acc = 0.f;
    for (int t = 0; t < 256; t++) acc += base[(size_t)t * DIN];
    g_xpart[(ch * BB + b) * DIN + d] = acc;
}
__global__ void k_xmean_fin()
{
    int b = blockIdx.x, d = threadIdx.x;
    float acc = 0.f;
    for (int ch = 0; ch < 16; ch++) acc += g_xpart[(ch * BB + b) * DIN + d];
    g_xmean[b * DIN + d] = acc * (1.0f / TT);
}

// ---------------------------------------------------------------------------
// Kernel 3: fused sal-finalize + PGD selector.
// 512 threads x 8 elems. Newton cap 3, exact-equality break (uniform).
// ---------------------------------------------------------------------------
__global__ __launch_bounds__(512) void k_selector(
    const float* __restrict__ b_sal, float* __restrict__ d_out)
{
    __shared__ float zsA[TT];
    __shared__ float zsB[TT];
    __shared__ float redS[2][16], redC[2][16];
    __shared__ float redT[2][16];
    __shared__ int   redi[2][16];

    const int b = blockIdx.x;
    const int tid = threadIdx.x;
    const int lane = tid & 31, wid = tid >> 5;   // 16 warps
    const int i0 = tid * 8;

    const float bs = b_sal[0];
    float s[8];
#pragma unroll
    for (int h = 0; h < 2; h++) {
        float4 p0 = *(const float4*)&g_spart[0][b * TT + i0 + h * 4];
        float4 p1 = *(const float4*)&g_spart[1][b * TT + i0 + h * 4];
        float4 p2 = *(const float4*)&g_spart[2][b * TT + i0 + h * 4];
        float4 p3 = *(const float4*)&g_spart[3][b * TT + i0 + h * 4];
        float zz[4];
        zz[0] = ((p0.x + p1.x) + p2.x) + p3.x + bs;
        zz[1] = ((p0.y + p1.y) + p2.y) + p3.y + bs;
        zz[2] = ((p0.z + p1.z) + p2.z) + p3.z + bs;
        zz[3] = ((p0.w + p1.w) + p2.w) + p3.w + bs;
        float4 so;
#pragma unroll
        for (int q = 0; q < 4; q++) {
            float v = fmaxf(zz[q], 0.f) + log1pf(expf(-fabsf(zz[q])));
            s[h * 4 + q] = v;
            ((float*)&so)[q] = v;
        }
        *(float4*)&g_sal[b * TT + i0 + h * 4] = so;
    }

    float y[8];
#pragma unroll
    for (int q = 0; q < 8; q++) y[q] = 0.0078125f;
    *(float4*)&zsA[i0] = make_float4(y[0], y[1], y[2], y[3]);
    *(float4*)&zsA[i0 + 4] = make_float4(y[4], y[5], y[6], y[7]);
    __syncthreads();

    float tau_prev = 0.f;
    for (int step = 0; step < PGD_STEPS; step++) {
        const float* rd = (step & 1) ? zsB : zsA;
        float*       wr = (step & 1) ? zsA : zsB;

        float yv[12];
        yv[0] = (i0 > 0) ? clip01(rd[i0 - 2] - tau_prev) : 0.f;
        yv[1] = (i0 > 0) ? clip01(rd[i0 - 1] - tau_prev) : 0.f;
#pragma unroll
        for (int q = 0; q < 8; q++) yv[2 + q] = y[q];
        yv[10] = (i0 + 8 < TT) ? clip01(rd[i0 + 8] - tau_prev) : 0.f;
        yv[11] = (i0 + 8 < TT) ? clip01(rd[i0 + 9] - tau_prev) : 0.f;

        float z[8];
#pragma unroll
        for (int q = 0; q < 8; q++) {
            float nb = ((yv[q + 3] + yv[q + 1]) + yv[q + 4]) + yv[q];
            float g = (s[q] - y[q]) - 0.5f * nb;
            z[q] = clip01(y[q] + 0.1f * g);
        }
        *(float4*)&wr[i0] = make_float4(z[0], z[1], z[2], z[3]);
        *(float4*)&wr[i0 + 4] = make_float4(z[4], z[5], z[6], z[7]);

        float tau = tau_prev;
        for (int it = 0; it < 3; it++) {
            const int p = it & 1;
            float ls = 0.f, lc = 0.f;
#pragma unroll
            for (int q = 0; q < 8; q++)
                if (z[q] > tau) { ls += z[q]; lc += 1.f; }
#pragma unroll
            for (int o = 16; o; o >>= 1) {
                ls += __shfl_xor_sync(0xffffffffu, ls, o);
                lc += __shfl_xor_sync(0xffffffffu, lc, o);
            }
            if (lane == 0) { redS[p][wid] = ls; redC[p][wid] = lc; }
            __syncthreads();
            float S = redS[p][lane & 15], C = redC[p][lane & 15];
#pragma unroll
            for (int o = 8; o; o >>= 1) {
                S += __shfl_xor_sync(0xffffffffu, S, o);
                C += __shfl_xor_sync(0xffffffffu, C, o);
            }
            float tnew = (C >= 1.f) ? fmaxf((S - 32.f) / C, 0.f) : 0.f;
            if (tnew == tau) break;     // uniform fixpoint
            tau = tnew;
        }
        tau_prev = tau;
#pragma unroll
        for (int q = 0; q < 8; q++)
            y[q] = clip01(z[q] - tau);
    }
    __syncthreads();

    float* outY = d_out + (size_t)BB * KSEL * DMODEL + (size_t)b * TT;
    *(float4*)&outY[i0] = make_float4(y[0], y[1], y[2], y[3]);
    *(float4*)&outY[i0 + 4] = make_float4(y[4], y[5], y[6], y[7]);

    {
        float ms = s[0];
#pragma unroll
        for (int q = 1; q < 8; q++) ms += s[q];
#pragma unroll
        for (int o = 16; o; o >>= 1) ms += __shfl_xor_sync(0xffffffffu, ms, o);
        if (lane == 0) redS[0][wid] = ms;
        __syncthreads();
        if (tid < 32) {
            float v = redS[0][lane & 15];
#pragma unroll
            for (int o = 8; o; o >>= 1) v += __shfl_xor_sync(0xffffffffu, v, o);
            if (lane == 0) g_msal[b] = v * (1.0f / TT);
        }
        __syncthreads();
    }

    float mval[8];
#pragma unroll
    for (int q = 0; q < 8; q++) mval[q] = y[q];
    for (int sel = 0; sel < KSEL; sel++) {
        const int p = sel & 1;
        float bv = -1.f; int bi = TT;
#pragma unroll
        for (int q = 0; q < 8; q++)
            if (mval[q] > bv) { bv = mval[q]; bi = i0 + q; }
#pragma unroll
        for (int o = 16; o; o >>= 1) {
            float ov = __shfl_xor_sync(0xffffffffu, bv, o);
            int   oi = __shfl_xor_sync(0xffffffffu, bi, o);
            if (ov > bv || (ov == bv && oi < bi)) { bv = ov; bi = oi; }
        }
        if (lane == 0) { redT[p][wid] = bv; redi[p][wid] = bi; }
        __syncthreads();
        bv = redT[p][lane & 15]; bi = redi[p][lane & 15];
#pragma unroll
        for (int o = 8; o; o >>= 1) {
            float ov = __shfl_xor_sync(0xffffffffu, bv, o);
            int   oi = __shfl_xor_sync(0xffffffffu, bi, o);
            if (ov > bv || (ov == bv && oi < bi)) { bv = ov; bi = oi; }
        }
        if (tid == 0) g_topidx[b * KSEL + sel] = bi;
        if ((bi >> 3) == tid) mval[bi & 7] = -1.f;
    }
}

// ---------------------------------------------------------------------------
// Kernel 4a: gather + anchor vector + lift (259->64) -> g_cloud
// ---------------------------------------------------------------------------
__global__ __launch_bounds__(256) void k_lift(
    const float* __restrict__ x, const float* __restrict__ mu,
    const float* __restrict__ sigma, const float* __restrict__ W_lift,
    const float* __restrict__ b_lift)
{
    __shared__ float u[AD];
    __shared__ float partl[4][KLIFT];
    const int b = blockIdx.x, j = blockIdx.y;
    const int tid = threadIdx.x;
    const int idx = g_topidx[b * KSEL + j];

    {
        float v = x[((size_t)b * TT + idx) * DIN + tid] - g_xmean[b * DIN + tid];
        u[tid] = (v - mu[tid]) / sigma[tid];
    }
    if (tid == 0) {
        float sali = g_sal[b * TT + idx];
        float ms = g_msal[b];
        u[256] = ((sali - ms) - mu[256]) / sigma[256];
        float tn = (float)idx * (1.0f / 4096.0f);
        u[257] = ((tn - 0.4998779296875f) - mu[257]) / sigma[257];
        float ds = (idx == 0) ? 0.f : (sali - g_sal[b * TT + idx - 1]);
        float mds = (g_sal[b * TT + TT - 1] - g_sal[b * TT]) * (1.0f / 4096.0f);
        u[258] = ((ds - mds) - mu[258]) / sigma[258];
    }
    __syncthreads();

    {
        const int kk = tid & 63, pp = tid >> 6;
        const int d0 = pp * 65;
        const int d1 = (pp == 3) ? AD : d0 + 65;
        float acc = 0.f;
        for (int d = d0; d < d1; d++)
            acc = fmaf(u[d], W_lift[d * KLIFT + kk], acc);
        partl[pp][kk] = acc;
    }
    __syncthreads();
    if (tid < KLIFT) {
        float v = b_lift[tid]
                + (((partl[0][tid] + partl[1][tid]) + partl[2][tid]) + partl[3][tid]);
        g_cloud[(b * KSEL + j) * KLIFT + tid] = v;
    }
}

// ---------------------------------------------------------------------------
// Kernel 4b: tokens = cloud[b,32,64] @ W_proj[64,1024] + b_proj
// ---------------------------------------------------------------------------
__global__ __launch_bounds__(256) void k_proj(
    const float* __restrict__ W_proj, const float* __restrict__ b_proj,
    float* __restrict__ out)
{
    __shared__ float sW[KLIFT][128];
    __shared__ float sC[KSEL][KLIFT];
    const int b = blockIdx.x, n0 = blockIdx.y * 128;
    const int tid = threadIdx.x;

#pragma unroll
    for (int it = 0; it < 8; it++) {
        int i = tid + it * 256;
        int k = i >> 5, c4 = i & 31;
        *(float4*)&sW[k][c4 * 4] =
            *(const float4*)&W_proj[(size_t)k * DMODEL + n0 + c4 * 4];
    }
#pragma unroll
    for (int it = 0; it < 2; it++) {
        int i = tid + it * 256;
        int r = i >> 4, c4 = i & 15;
        *(float4*)&sC[r][c4 * 4] =
            *(const float4*)&g_cloud[(b * KSEL + r) * KLIFT + c4 * 4];
    }
    __syncthreads();

    const int r = tid >> 3;
    const int c0 = (tid & 7) * 16;
    float4 acc[4];
#pragma unroll
    for (int i = 0; i < 4; i++)
        acc[i] = *(const float4*)&b_proj[n0 + c0 + i * 4];
#pragma unroll
    for (int k = 0; k < KLIFT; k++) {
        float a = sC[r][k];
#pragma unroll
        for (int i = 0; i < 4; i++) {
            float4 w = *(const float4*)&sW[k][c0 + i * 4];
            acc[i].x = fmaf(a, w.x, acc[i].x);
            acc[i].y = fmaf(a, w.y, acc[i].y);
            acc[i].z = fmaf(a, w.z, acc[i].z);
            acc[i].w = fmaf(a, w.w, acc[i].w);
        }
    }
    float* o = out + ((size_t)(b * KSEL + r)) * DMODEL + n0 + c0;
#pragma unroll
    for (int i = 0; i < 4; i++) *(float4*)&o[i * 4] = acc[i];
}

// ---------------------------------------------------------------------------
extern "C" void kernel_launch(void* const* d_in, const int* in_sizes, int n_in,
                              void* d_out, int out_size)
{
    const float* x      = (const float*)d_in[0];
    const float* W1     = (const float*)d_in[1];
    const float* b1     = (const float*)d_in[2];
    const float* w_sal  = (const float*)d_in[5];
    const float* b_sal  = (const float*)d_in[6];
    const float* mu     = (const float*)d_in[7];
    const float* sigma  = (const float*)d_in[8];
    const float* W_lift = (const float*)d_in[9];
    const float* b_lift = (const float*)d_in[10];
    const float* W_proj = (const float*)d_in[11];
    const float* b_proj = (const float*)d_in[12];
    float* out = (float*)d_out;

    static cudaStream_t s2 = []() {
        cudaStream_t s; cudaStreamCreateWithFlags(&s, cudaStreamNonBlocking); return s;
    }();
    static cudaEvent_t evG = []() {
        cudaEvent_t e; cudaEventCreateWithFlags(&e, cudaEventDisableTiming); return e;
    }();
    static cudaEvent_t evJ = []() {
        cudaEvent_t e; cudaEventCreateWithFlags(&e, cudaEventDisableTiming); return e;
    }();

    // main: convert -> gemm -> selector (32 CTAs)
    k_convert_w<<<dim3(64, 16), 128>>>(W1);
    k_gemm_part<<<dim3(4, 1024), 256>>>(x, b1, w_sal);
    cudaEventRecord(evG, 0);
    k_selector<<<BB, 512>>>(b_sal, out);

    // side: xmean runs in the selector's shadow (116 idle SMs)
    cudaStreamWaitEvent(s2, evG, 0);
    k_xmean_part<<<dim3(BB, 16), 256, 0, s2>>>(x);
    k_xmean_fin<<<BB, 256, 0, s2>>>();
    cudaEventRecord(evJ, s2);

    cudaStreamWaitEvent(0, evJ, 0);
    k_lift<<<dim3(BB, KSEL), 256>>>(x, mu, sigma, W_lift, b_lift);
    k_proj<<<dim3(BB, 8), 256>>>(W_proj, b_proj, out);
}